// round 12
// baseline (speedup 1.0000x reference)
#include <cuda_runtime.h>
#include <cuda_bf16.h>
#include <cstdint>

#define BB 4
#define TT 4096
#define DD 768
#define HH 64
#define BT (BB*TT)
#define NSPLIT 4
#define MCONST 16.0f

// Scratch. g_Q: pre-scaled (x0.125*log2e) + tf32-rounded, h-PERMUTED.
// g_K: tf32-rounded, h-PERMUTED. g_Vt: V transposed [b][h][t], t-PERMUTED.
// Permutation within each 8-group: original 8a+4s+c  ->  position 8a+2c+s.
__device__ float  g_Q[BT * HH];
__device__ float  g_K[BT * HH];
__device__ float  g_Vt[BB * HH * TT];
__device__ float2 g_Wsp[DD * 192];
__device__ float  g_pO[NSPLIT * BT * HH];   // partial O (scale 2^-MCONST)
__device__ float  g_pl[NSPLIT * BT];        // partial denom (same scale)

// ---------------------------------------------------------------------------
// helpers
// ---------------------------------------------------------------------------
__device__ __forceinline__ uint32_t f2tf(float f) {
    uint32_t u;
    asm("cvt.rna.tf32.f32 %0, %1;" : "=r"(u) : "f"(f));
    return u;
}
__device__ __forceinline__ float tf32f(float f) {
    return __uint_as_float(f2tf(f));
}
__device__ __forceinline__ float ex2(float x) {
    float y;
    asm("ex2.approx.f32 %0, %1;" : "=f"(y) : "f"(x));
    return y;
}
__device__ __forceinline__ int permh(int h) {
    return (h & ~7) + ((h & 3) << 1) + ((h >> 2) & 1);
}

__device__ __forceinline__ void mma_tf32(float d[4], const uint32_t a[4],
                                         uint32_t b0, uint32_t b1) {
    asm volatile(
        "mma.sync.aligned.m16n8k8.row.col.f32.tf32.tf32.f32 "
        "{%0,%1,%2,%3}, {%4,%5,%6,%7}, {%8,%9}, {%0,%1,%2,%3};"
        : "+f"(d[0]), "+f"(d[1]), "+f"(d[2]), "+f"(d[3])
        : "r"(a[0]), "r"(a[1]), "r"(a[2]), "r"(a[3]), "r"(b0), "r"(b1));
}

__device__ __forceinline__ void cpa16(uint32_t smem_dst, const void* gsrc) {
    asm volatile("cp.async.cg.shared.global [%0], [%1], 16;"
                 :: "r"(smem_dst), "l"(gsrc));
}
__device__ __forceinline__ void cpa_commit() {
    asm volatile("cp.async.commit_group;");
}
__device__ __forceinline__ void cpa_wait0() {
    asm volatile("cp.async.wait_group 0;" ::: "memory");
}

// ---------------------------------------------------------------------------
// Kernel 0: split W = [Wq|Wk|Wv] into (hi, lo) tf32 pair.
// ---------------------------------------------------------------------------
__global__ __launch_bounds__(256) void prep_w(
    const float* __restrict__ Wq, const float* __restrict__ Wk,
    const float* __restrict__ Wv)
{
    int i = blockIdx.x * 256 + threadIdx.x;
    if (i >= DD * 192) return;
    int k = i / 192, n = i % 192;
    float v = (n < 64) ? Wq[k * 64 + n]
            : (n < 128) ? Wk[k * 64 + n - 64]
            : Wv[k * 64 + n - 128];
    float hi = tf32f(v);
    float lo = tf32f(v - hi);
    g_Wsp[i] = make_float2(hi, lo);
}

// ---------------------------------------------------------------------------
// Kernel 1: QKV projection, tensor cores, 3-term tf32 split, sw-pipelined.
// BN=192 in ONE CTA (512 thr, 16 warps): x tile read ONCE (halves x traffic
// vs the 2-block R11 grid). Warp (mg=w>>2, ng=w&3): rows mg*32 (2 m16 tiles),
// cols ng*48 (6 nb). Bit-identical math/output to R11.
// ---------------------------------------------------------------------------
#define QSCALE (0.125f * 1.4426950408889634f)

__global__ __launch_bounds__(512) void qkv_mma(const float* __restrict__ x)
{
    extern __shared__ float qsm[];
    float*  xs = qsm;                          // 128 x 36 floats
    float4* wf = (float4*)(qsm + 128 * 36);    // [4 kb * 24 nb][33] float4

    const int tid = threadIdx.x;
    const int w   = tid >> 5;
    const int l   = tid & 31;
    const int mg  = w >> 2;                    // 0..3
    const int ng  = w & 3;                     // 0..3
    const int row0 = blockIdx.x * 128;

    float acc[2][6][4];
    #pragma unroll
    for (int mt = 0; mt < 2; mt++)
        #pragma unroll
        for (int nb = 0; nb < 6; nb++)
            acc[mt][nb][0] = acc[mt][nb][1] = acc[mt][nb][2] = acc[mt][nb][3] = 0.0f;

    float4 px[2];
    float2 pw[12];

    #pragma unroll
    for (int t = 0; t < 2; t++) {
        int f  = tid + t * 512;
        int r  = f >> 3;
        int c4 = (f & 7) * 4;
        px[t] = *(const float4*)&x[(size_t)(row0 + r) * DD + c4];
    }
    #pragma unroll
    for (int t = 0; t < 12; t++) {
        int i  = tid + t * 512;                // 0..6143
        int kk = i / 192;
        int nn = i % 192;
        pw[t] = g_Wsp[(size_t)kk * 192 + nn];
    }

    for (int k0 = 0; k0 < DD; k0 += 32) {
        #pragma unroll
        for (int t = 0; t < 2; t++) {
            int f  = tid + t * 512;
            int r  = f >> 3;
            int c4 = (f & 7) * 4;
            *(float4*)&xs[r * 36 + c4] = px[t];
        }
        #pragma unroll
        for (int t = 0; t < 12; t++) {
            int i  = tid + t * 512;
            int kk = i / 192;
            int nn = i % 192;
            int kb   = kk >> 3, kr = kk & 7;
            int slot = kr >> 2;
            int nb   = nn >> 3;
            int lane = ((nn & 7) << 2) | (kr & 3);
            float* p = (float*)&wf[(kb * 24 + nb) * 33 + lane];
            p[slot]     = pw[t].x;
            p[2 + slot] = pw[t].y;
        }
        __syncthreads();

        if (k0 + 32 < DD) {
            #pragma unroll
            for (int t = 0; t < 2; t++) {
                int f  = tid + t * 512;
                int r  = f >> 3;
                int c4 = (f & 7) * 4;
                px[t] = *(const float4*)&x[(size_t)(row0 + r) * DD + k0 + 32 + c4];
            }
            #pragma unroll
            for (int t = 0; t < 12; t++) {
                int i  = tid + t * 512;
                int kk = i / 192;
                int nn = i % 192;
                pw[t] = g_Wsp[(size_t)(k0 + 32 + kk) * 192 + nn];
            }
        }

        #pragma unroll
        for (int kb = 0; kb < 4; kb++) {
            uint32_t ahi[2][4], alo[2][4];
            #pragma unroll
            for (int mt = 0; mt < 2; mt++) {
                const int rA = mg * 32 + mt * 16 + (l >> 2);
                const int cA = kb * 8 + (l & 3);
                float a0 = xs[rA * 36 + cA];
                float a1 = xs[(rA + 8) * 36 + cA];
                float a2 = xs[rA * 36 + cA + 4];
                float a3 = xs[(rA + 8) * 36 + cA + 4];
                ahi[mt][0] = f2tf(a0); alo[mt][0] = f2tf(a0 - __uint_as_float(ahi[mt][0]));
                ahi[mt][1] = f2tf(a1); alo[mt][1] = f2tf(a1 - __uint_as_float(ahi[mt][1]));
                ahi[mt][2] = f2tf(a2); alo[mt][2] = f2tf(a2 - __uint_as_float(ahi[mt][2]));
                ahi[mt][3] = f2tf(a3); alo[mt][3] = f2tf(a3 - __uint_as_float(ahi[mt][3]));
            }
            #pragma unroll
            for (int nb = 0; nb < 6; nb++) {
                float4 q = wf[(kb * 24 + ng * 6 + nb) * 33 + l];
                uint32_t bh0 = __float_as_uint(q.x), bh1 = __float_as_uint(q.y);
                uint32_t bl0 = __float_as_uint(q.z), bl1 = __float_as_uint(q.w);
                #pragma unroll
                for (int mt = 0; mt < 2; mt++) {
                    mma_tf32(acc[mt][nb], ahi[mt], bh0, bh1);
                    mma_tf32(acc[mt][nb], ahi[mt], bl0, bl1);
                    mma_tf32(acc[mt][nb], alo[mt], bh0, bh1);
                }
            }
        }
        __syncthreads();
    }

    #pragma unroll
    for (int mt = 0; mt < 2; mt++) {
        #pragma unroll
        for (int nb = 0; nb < 6; nb++) {
            const int rowa  = row0 + mg * 32 + mt * 16 + (l >> 2);
            const int nglob = ng * 48 + nb * 8 + (l & 3) * 2;
            const int mat   = nglob >> 6;
            const int col   = nglob & 63;
            if (mat == 0) {
                const int p0 = permh(col), p1 = permh(col + 1);
                g_Q[(size_t)rowa * HH + p0]       = tf32f(QSCALE * acc[mt][nb][0]);
                g_Q[(size_t)rowa * HH + p1]       = tf32f(QSCALE * acc[mt][nb][1]);
                g_Q[(size_t)(rowa + 8) * HH + p0] = tf32f(QSCALE * acc[mt][nb][2]);
                g_Q[(size_t)(rowa + 8) * HH + p1] = tf32f(QSCALE * acc[mt][nb][3]);
            } else if (mat == 1) {
                const int p0 = permh(col), p1 = permh(col + 1);
                g_K[(size_t)rowa * HH + p0]       = tf32f(acc[mt][nb][0]);
                g_K[(size_t)rowa * HH + p1]       = tf32f(acc[mt][nb][1]);
                g_K[(size_t)(rowa + 8) * HH + p0] = tf32f(acc[mt][nb][2]);
                g_K[(size_t)(rowa + 8) * HH + p1] = tf32f(acc[mt][nb][3]);
            } else {
                const int bb = rowa >> 12;
                const int t0 = rowa & 4095;
                const int pt = (t0 & ~7) + ((t0 & 3) << 1) + ((t0 >> 2) & 1);
                g_Vt[((size_t)(bb << 6) + col    ) * TT + pt    ] = acc[mt][nb][0];
                g_Vt[((size_t)(bb << 6) + col + 1) * TT + pt    ] = acc[mt][nb][1];
                g_Vt[((size_t)(bb << 6) + col    ) * TT + pt + 8] = acc[mt][nb][2];
                g_Vt[((size_t)(bb << 6) + col + 1) * TT + pt + 8] = acc[mt][nb][3];
            }
        }
    }
}

// ---------------------------------------------------------------------------
// Kernel 2: causal flash attention (unchanged from R11 — fixed-max softmax).
// ---------------------------------------------------------------------------
__global__ __launch_bounds__(128, 3) void attn_kernel()
{
    extern __shared__ float sm[];   // [buf][K 4096 | Vt 4096] floats

    const int tid = threadIdx.x;
    const int w   = tid >> 5;
    const int l   = tid & 31;
    const int r   = l >> 2;
    const int c   = l & 3;

    const int bid = blockIdx.x;
    const int qt  = 63 - (bid >> 4);
    const int b   = (bid >> 2) & 3;
    const int s   = bid & 3;
    const int q0  = qt * 64;
    const size_t base = (size_t)b * TT * HH;

    const int nt    = qt + 1;
    const int chunk = (nt + NSPLIT - 1) >> 2;
    const int ktbeg = min(s * chunk, nt);
    const int ktend = min(ktbeg + chunk, nt);

    const int rowg  = q0 + w * 16 + r;
    const int rowg8 = rowg + 8;

    float o[8][4];
    #pragma unroll
    for (int hb = 0; hb < 8; hb++)
        o[hb][0] = o[hb][1] = o[hb][2] = o[hb][3] = 0.0f;
    float lR = 0.0f, lR8 = 0.0f;

    if (ktbeg < ktend) {
        const uint32_t sb = (uint32_t)__cvta_generic_to_shared(sm);

        const int crow = tid >> 4;
        const int cq   = tid & 15;

        uint32_t qf[8][4];
        #pragma unroll
        for (int kb = 0; kb < 8; kb++) {
            float2 a0 = *(const float2*)&g_Q[base + (size_t)rowg  * HH + kb * 8 + 2 * c];
            float2 a1 = *(const float2*)&g_Q[base + (size_t)rowg8 * HH + kb * 8 + 2 * c];
            qf[kb][0] = __float_as_uint(a0.x);
            qf[kb][2] = __float_as_uint(a0.y);
            qf[kb][1] = __float_as_uint(a1.x);
            qf[kb][3] = __float_as_uint(a1.y);
        }

        auto issue = [&](int bf, int jb) {
            #pragma unroll
            for (int i = 0; i < 8; i++) {
                const int row = crow + i * 8;
                const uint32_t swz = (uint32_t)((cq ^ ((row & 3) << 1)) << 4);
                cpa16(sb + (uint32_t)bf * 32768u + (uint32_t)row * 256u + swz,
                      &g_K[base + (size_t)(jb + row) * HH + cq * 4]);
                cpa16(sb + (uint32_t)bf * 32768u + 16384u + (uint32_t)row * 256u + swz,
                      &g_Vt[((size_t)(b << 6) + row) * TT + jb + cq * 4]);
            }
            cpa_commit();
        };

        issue(0, ktbeg * 64);

        int cur = 0;
        const int qs1 = (l & 28) | (c >> 1);
        const int qs2 = qs1 + 2;
        const int rx  = (r & 3) << 1;
        const int boff = 2 * (c & 1);
        const int cc  = c >> 1;

        for (int kt = ktbeg; kt < ktend; kt++) {
            const int jbase = kt * 64;
            cpa_wait0();
            __syncthreads();
            if (kt + 1 < ktend) issue(cur ^ 1, jbase + 64);

            const float* kp = sm + cur * 8192;
            const float* vp = kp + 4096;

            float sS[8][4];
            #pragma unroll
            for (int nb = 0; nb < 8; nb++)
                sS[nb][0] = sS[nb][1] = sS[nb][2] = sS[nb][3] = 0.0f;
            #pragma unroll
            for (int nb = 0; nb < 8; nb++) {
                const float* rowp = kp + (nb * 8 + r) * 64;
                #pragma unroll
                for (int kb = 0; kb < 8; kb++) {
                    float2 t = *(const float2*)&rowp[(((2 * kb + cc) ^ rx) << 2) + boff];
                    mma_tf32(sS[nb], qf[kb],
                             __float_as_uint(t.x), __float_as_uint(t.y));
                }
            }

            if (kt == qt) {
                #pragma unroll
                for (int nb = 0; nb < 8; nb++) {
                    const int col = jbase + nb * 8 + 2 * c;
                    if (col     > rowg ) sS[nb][0] = -1.0e30f;
                    if (col + 1 > rowg ) sS[nb][1] = -1.0e30f;
                    if (col     > rowg8) sS[nb][2] = -1.0e30f;
                    if (col + 1 > rowg8) sS[nb][3] = -1.0e30f;
                }
            }

            float sum0 = 0.0f, sum1 = 0.0f;
            #pragma unroll
            for (int nb = 0; nb < 8; nb++) {
                sS[nb][0] = ex2(sS[nb][0] - MCONST);
                sS[nb][1] = ex2(sS[nb][1] - MCONST);
                sS[nb][2] = ex2(sS[nb][2] - MCONST);
                sS[nb][3] = ex2(sS[nb][3] - MCONST);
                sum0 += sS[nb][0] + sS[nb][1];
                sum1 += sS[nb][2] + sS[nb][3];
            }
            lR  += sum0;
            lR8 += sum1;

            #pragma unroll
            for (int kb = 0; kb < 8; kb++) {
                float e, od;
                uint32_t a[4];
                e  = __shfl_sync(0xffffffffu, sS[kb][0], qs1);
                od = __shfl_sync(0xffffffffu, sS[kb][1], qs1);
                a[0] = __float_as_uint((c & 1) ? od : e);
                e  = __shfl_sync(0xffffffffu, sS[kb][2], qs1);
                od = __shfl_sync(0xffffffffu, sS[kb][3], qs1);
                a[1] = __float_as_uint((c & 1) ? od : e);
                e  = __shfl_sync(0xffffffffu, sS[kb][0], qs2);
                od = __shfl_sync(0xffffffffu, sS[kb][1], qs2);
                a[2] = __float_as_uint((c & 1) ? od : e);
                e  = __shfl_sync(0xffffffffu, sS[kb][2], qs2);
                od = __shfl_sync(0xffffffffu, sS[kb][3], qs2);
                a[3] = __float_as_uint((c & 1) ? od : e);

                #pragma unroll
                for (int hb = 0; hb < 8; hb++) {
                    const float* rowp = vp + (hb * 8 + r) * 64;
                    float2 t = *(const float2*)&rowp[(((2 * kb + cc) ^ rx) << 2) + boff];
                    mma_tf32(o[hb], a, __float_as_uint(t.x), __float_as_uint(t.y));
                }
            }
            cur ^= 1;
        }
    }

    lR  += __shfl_xor_sync(0xffffffffu, lR, 1);
    lR  += __shfl_xor_sync(0xffffffffu, lR, 2);
    lR8 += __shfl_xor_sync(0xffffffffu, lR8, 1);
    lR8 += __shfl_xor_sync(0xffffffffu, lR8, 2);

    const size_t pr  = (size_t)(s * BB + b) * TT + rowg;
    const size_t pr8 = pr + 8;
    #pragma unroll
    for (int hb = 0; hb < 8; hb++) {
        *(float2*)&g_pO[pr  * HH + hb * 8 + 2 * c] = make_float2(o[hb][0], o[hb][1]);
        *(float2*)&g_pO[pr8 * HH + hb * 8 + 2 * c] = make_float2(o[hb][2], o[hb][3]);
    }
    if (c == 0) {
        g_pl[pr]  = lR;
        g_pl[pr8] = lR8;
    }
}

// ---------------------------------------------------------------------------
// Kernel 3: merge the four kv-splits (unit weights: common fixed max).
// ---------------------------------------------------------------------------
__global__ __launch_bounds__(256) void combine_kernel(float* __restrict__ out)
{
    const int gid  = blockIdx.x * 256 + threadIdx.x;
    const int rowg = gid >> 4;
    const int col  = (gid & 15) * 4;

    float denom = 0.0f;
    #pragma unroll
    for (int sp = 0; sp < NSPLIT; sp++)
        denom += g_pl[sp * BT + rowg];
    const float inv = 1.0f / denom;

    float4 acc = make_float4(0.f, 0.f, 0.f, 0.f);
    #pragma unroll
    for (int sp = 0; sp < NSPLIT; sp++) {
        float4 O = *(const float4*)&g_pO[((size_t)sp * BT + rowg) * HH + col];
        acc.x += O.x;
        acc.y += O.y;
        acc.z += O.z;
        acc.w += O.w;
    }
    acc.x *= inv; acc.y *= inv; acc.z *= inv; acc.w *= inv;
    *(float4*)&out[(size_t)rowg * HH + col] = acc;
}

// ---------------------------------------------------------------------------
extern "C" void kernel_launch(void* const* d_in, const int* in_sizes, int n_in,
                              void* d_out, int out_size)
{
    const float* x  = (const float*)d_in[0];
    const float* Wq = (const float*)d_in[1];
    const float* Wk = (const float*)d_in[2];
    const float* Wv = (const float*)d_in[3];
    float* out = (float*)d_out;

    const int attn_smem = 2 * 2 * 4096 * sizeof(float);              // 64 KB
    const int qkv_smem  = (128 * 36) * 4 + (4 * 24 * 33) * 16;       // ~67.5 KB
    cudaFuncSetAttribute(attn_kernel, cudaFuncAttributeMaxDynamicSharedMemorySize,
                         attn_smem);
    cudaFuncSetAttribute(qkv_mma, cudaFuncAttributeMaxDynamicSharedMemorySize,
                         qkv_smem);

    prep_w<<<(DD * 192 + 255) / 256, 256>>>(Wq, Wk, Wv);
    qkv_mma<<<BT / 128, 512, qkv_smem>>>(x);
    attn_kernel<<<64 * BB * NSPLIT, 128, attn_smem>>>();
    combine_kernel<<<(BT * HH / 4) / 256, 256>>>(out);
}

// round 13
// speedup vs baseline: 1.1093x; 1.1093x over previous
#include <cuda_runtime.h>
#include <cuda_fp16.h>
#include <cstdint>

#define BB 4
#define TT 4096
#define DD 768
#define HH 64
#define BT (BB*TT)
#define NSPLIT 4
#define MCONST 16.0f

// Scratch. g_Q: pre-scaled (x0.125*log2e) + tf32-rounded, h-PERMUTED.
// g_K: tf32-rounded, h-PERMUTED.
// g_Vth: V fp16, transposed [b][h][t], t PAIR-PERMUTED:
//   within each 16-t group, pair p=(t>>1)&7 = 4s+c -> position 2c+s
//   (so fp16 B-fragment pairs (c, c+4) become adjacent -> one LDS.64).
__device__ float  g_Q[BT * HH];
__device__ float  g_K[BT * HH];
__device__ __half g_Vth[BB * HH * TT];
__device__ float2 g_Wsp[DD * 192];
__device__ float  g_pO[NSPLIT * BT * HH];   // partial O (scale 2^-MCONST)
__device__ float  g_pl[NSPLIT * BT];        // partial denom (same scale)

// ---------------------------------------------------------------------------
// helpers
// ---------------------------------------------------------------------------
__device__ __forceinline__ uint32_t f2tf(float f) {
    uint32_t u;
    asm("cvt.rna.tf32.f32 %0, %1;" : "=r"(u) : "f"(f));
    return u;
}
__device__ __forceinline__ float tf32f(float f) {
    return __uint_as_float(f2tf(f));
}
__device__ __forceinline__ float ex2(float x) {
    float y;
    asm("ex2.approx.f32 %0, %1;" : "=f"(y) : "f"(x));
    return y;
}
__device__ __forceinline__ int permh(int h) {
    return (h & ~7) + ((h & 3) << 1) + ((h >> 2) & 1);
}
// pack (lo, hi) floats -> f16x2 (lo in low half)
__device__ __forceinline__ uint32_t pack_h2(float lo, float hi) {
    uint32_t u;
    asm("cvt.rn.f16x2.f32 %0, %1, %2;" : "=r"(u) : "f"(hi), "f"(lo));
    return u;
}

__device__ __forceinline__ void mma_tf32(float d[4], const uint32_t a[4],
                                         uint32_t b0, uint32_t b1) {
    asm volatile(
        "mma.sync.aligned.m16n8k8.row.col.f32.tf32.tf32.f32 "
        "{%0,%1,%2,%3}, {%4,%5,%6,%7}, {%8,%9}, {%0,%1,%2,%3};"
        : "+f"(d[0]), "+f"(d[1]), "+f"(d[2]), "+f"(d[3])
        : "r"(a[0]), "r"(a[1]), "r"(a[2]), "r"(a[3]), "r"(b0), "r"(b1));
}

__device__ __forceinline__ void mma_f16(float d[4], const uint32_t a[4],
                                        uint32_t b0, uint32_t b1) {
    asm volatile(
        "mma.sync.aligned.m16n8k16.row.col.f32.f16.f16.f32 "
        "{%0,%1,%2,%3}, {%4,%5,%6,%7}, {%8,%9}, {%0,%1,%2,%3};"
        : "+f"(d[0]), "+f"(d[1]), "+f"(d[2]), "+f"(d[3])
        : "r"(a[0]), "r"(a[1]), "r"(a[2]), "r"(a[3]), "r"(b0), "r"(b1));
}

__device__ __forceinline__ void cpa16(uint32_t smem_dst, const void* gsrc) {
    asm volatile("cp.async.cg.shared.global [%0], [%1], 16;"
                 :: "r"(smem_dst), "l"(gsrc));
}
__device__ __forceinline__ void cpa_commit() {
    asm volatile("cp.async.commit_group;");
}
__device__ __forceinline__ void cpa_wait0() {
    asm volatile("cp.async.wait_group 0;" ::: "memory");
}

// ---------------------------------------------------------------------------
// Kernel 0: split W = [Wq|Wk|Wv] into (hi, lo) tf32 pair.
// ---------------------------------------------------------------------------
__global__ __launch_bounds__(256) void prep_w(
    const float* __restrict__ Wq, const float* __restrict__ Wk,
    const float* __restrict__ Wv)
{
    int i = blockIdx.x * 256 + threadIdx.x;
    if (i >= DD * 192) return;
    int k = i / 192, n = i % 192;
    float v = (n < 64) ? Wq[k * 64 + n]
            : (n < 128) ? Wk[k * 64 + n - 64]
            : Wv[k * 64 + n - 128];
    float hi = tf32f(v);
    float lo = tf32f(v - hi);
    g_Wsp[i] = make_float2(hi, lo);
}

// ---------------------------------------------------------------------------
// Kernel 1: QKV projection (R11 two-block shape — reverted, known best).
// Epilogue: Q scaled+rounded h-permuted, K rounded h-permuted,
// V fp16 transposed [b][h][t] with pair-permuted t.
// ---------------------------------------------------------------------------
#define QSCALE (0.125f * 1.4426950408889634f)

__global__ __launch_bounds__(256) void qkv_mma(const float* __restrict__ x)
{
    __shared__ float  xs[128 * 36];
    __shared__ float4 wf[4 * 12 * 33];

    const int tid = threadIdx.x;
    const int w   = tid >> 5;
    const int l   = tid & 31;
    const int mg  = w >> 1;
    const int ng  = w & 1;
    const int row0 = (blockIdx.x >> 1) * 128;
    const int n0   = (blockIdx.x & 1) * 96;

    float acc[2][6][4];
    #pragma unroll
    for (int mt = 0; mt < 2; mt++)
        #pragma unroll
        for (int nb = 0; nb < 6; nb++)
            acc[mt][nb][0] = acc[mt][nb][1] = acc[mt][nb][2] = acc[mt][nb][3] = 0.0f;

    float4 px[4];
    float2 pw[12];

    #pragma unroll
    for (int t = 0; t < 4; t++) {
        int f  = tid + t * 256;
        int r  = f >> 3;
        int c4 = (f & 7) * 4;
        px[t] = *(const float4*)&x[(size_t)(row0 + r) * DD + c4];
    }
    #pragma unroll
    for (int t = 0; t < 12; t++) {
        int i  = tid + t * 256;
        int kk = i / 96;
        int nn = i % 96;
        pw[t] = g_Wsp[(size_t)kk * 192 + n0 + nn];
    }

    for (int k0 = 0; k0 < DD; k0 += 32) {
        #pragma unroll
        for (int t = 0; t < 4; t++) {
            int f  = tid + t * 256;
            int r  = f >> 3;
            int c4 = (f & 7) * 4;
            *(float4*)&xs[r * 36 + c4] = px[t];
        }
        #pragma unroll
        for (int t = 0; t < 12; t++) {
            int i  = tid + t * 256;
            int kk = i / 96;
            int nn = i % 96;
            int kb   = kk >> 3, kr = kk & 7;
            int slot = kr >> 2;
            int nb   = nn >> 3;
            int lane = ((nn & 7) << 2) | (kr & 3);
            float* p = (float*)&wf[(kb * 12 + nb) * 33 + lane];
            p[slot]     = pw[t].x;
            p[2 + slot] = pw[t].y;
        }
        __syncthreads();

        if (k0 + 32 < DD) {
            #pragma unroll
            for (int t = 0; t < 4; t++) {
                int f  = tid + t * 256;
                int r  = f >> 3;
                int c4 = (f & 7) * 4;
                px[t] = *(const float4*)&x[(size_t)(row0 + r) * DD + k0 + 32 + c4];
            }
            #pragma unroll
            for (int t = 0; t < 12; t++) {
                int i  = tid + t * 256;
                int kk = i / 96;
                int nn = i % 96;
                pw[t] = g_Wsp[(size_t)(k0 + 32 + kk) * 192 + n0 + nn];
            }
        }

        #pragma unroll
        for (int kb = 0; kb < 4; kb++) {
            uint32_t ahi[2][4], alo[2][4];
            #pragma unroll
            for (int mt = 0; mt < 2; mt++) {
                const int rA = mg * 32 + mt * 16 + (l >> 2);
                const int cA = kb * 8 + (l & 3);
                float a0 = xs[rA * 36 + cA];
                float a1 = xs[(rA + 8) * 36 + cA];
                float a2 = xs[rA * 36 + cA + 4];
                float a3 = xs[(rA + 8) * 36 + cA + 4];
                ahi[mt][0] = f2tf(a0); alo[mt][0] = f2tf(a0 - __uint_as_float(ahi[mt][0]));
                ahi[mt][1] = f2tf(a1); alo[mt][1] = f2tf(a1 - __uint_as_float(ahi[mt][1]));
                ahi[mt][2] = f2tf(a2); alo[mt][2] = f2tf(a2 - __uint_as_float(ahi[mt][2]));
                ahi[mt][3] = f2tf(a3); alo[mt][3] = f2tf(a3 - __uint_as_float(ahi[mt][3]));
            }
            #pragma unroll
            for (int nb = 0; nb < 6; nb++) {
                float4 q = wf[(kb * 12 + ng * 6 + nb) * 33 + l];
                uint32_t bh0 = __float_as_uint(q.x), bh1 = __float_as_uint(q.y);
                uint32_t bl0 = __float_as_uint(q.z), bl1 = __float_as_uint(q.w);
                #pragma unroll
                for (int mt = 0; mt < 2; mt++) {
                    mma_tf32(acc[mt][nb], ahi[mt], bh0, bh1);
                    mma_tf32(acc[mt][nb], ahi[mt], bl0, bl1);
                    mma_tf32(acc[mt][nb], alo[mt], bh0, bh1);
                }
            }
        }
        __syncthreads();
    }

    #pragma unroll
    for (int mt = 0; mt < 2; mt++) {
        #pragma unroll
        for (int nb = 0; nb < 6; nb++) {
            const int rowa  = row0 + mg * 32 + mt * 16 + (l >> 2);
            const int nglob = n0 + ng * 48 + nb * 8 + (l & 3) * 2;
            const int mat   = nglob >> 6;
            const int col   = nglob & 63;
            if (mat == 0) {
                const int p0 = permh(col), p1 = permh(col + 1);
                g_Q[(size_t)rowa * HH + p0]       = tf32f(QSCALE * acc[mt][nb][0]);
                g_Q[(size_t)rowa * HH + p1]       = tf32f(QSCALE * acc[mt][nb][1]);
                g_Q[(size_t)(rowa + 8) * HH + p0] = tf32f(QSCALE * acc[mt][nb][2]);
                g_Q[(size_t)(rowa + 8) * HH + p1] = tf32f(QSCALE * acc[mt][nb][3]);
            } else if (mat == 1) {
                const int p0 = permh(col), p1 = permh(col + 1);
                g_K[(size_t)rowa * HH + p0]       = tf32f(acc[mt][nb][0]);
                g_K[(size_t)rowa * HH + p1]       = tf32f(acc[mt][nb][1]);
                g_K[(size_t)(rowa + 8) * HH + p0] = tf32f(acc[mt][nb][2]);
                g_K[(size_t)(rowa + 8) * HH + p1] = tf32f(acc[mt][nb][3]);
            } else {
                // V fp16, transposed [b][h][t], pair-permuted t.
                // tperm(t0) and tperm(t0+8) = tperm(t0)+2 (t0&15 < 8 here).
                const int bb = rowa >> 12;
                const int t0 = rowa & 4095;
                const int q2 = (t0 >> 1) & 3;
                const int tp = (t0 & ~15) | (q2 << 2) | (t0 & 1);
                __half* v0 = g_Vth + (size_t)((bb << 6) + col) * TT;
                __half* v1 = g_Vth + (size_t)((bb << 6) + col + 1) * TT;
                v0[tp]     = __float2half_rn(acc[mt][nb][0]);
                v1[tp]     = __float2half_rn(acc[mt][nb][1]);
                v0[tp + 2] = __float2half_rn(acc[mt][nb][2]);
                v1[tp + 2] = __float2half_rn(acc[mt][nb][3]);
            }
        }
    }
}

// ---------------------------------------------------------------------------
// Kernel 2: causal flash attention, split-kv (4), fixed-max softmax.
// S: tf32 MMA (unchanged). PV: fp16 m16n8k16 MMA — S accumulator fragments
// convert in-register to A-fragments (NO shfl exchange); V fp16 B-frags via
// single LDS.64 (pair-permuted storage). Buffers 24 KB -> 4 CTAs/SM.
// ---------------------------------------------------------------------------
__global__ __launch_bounds__(128, 4) void attn_kernel()
{
    extern __shared__ float sm[];   // [buf][K 4096 floats | Vth 4096 halves]

    const int tid = threadIdx.x;
    const int w   = tid >> 5;
    const int l   = tid & 31;
    const int r   = l >> 2;
    const int c   = l & 3;

    const int bid = blockIdx.x;
    const int qt  = 63 - (bid >> 4);
    const int b   = (bid >> 2) & 3;
    const int s   = bid & 3;
    const int q0  = qt * 64;
    const size_t base = (size_t)b * TT * HH;

    const int nt    = qt + 1;
    const int chunk = (nt + NSPLIT - 1) >> 2;
    const int ktbeg = min(s * chunk, nt);
    const int ktend = min(ktbeg + chunk, nt);

    const int rowg  = q0 + w * 16 + r;
    const int rowg8 = rowg + 8;

    float o[8][4];
    #pragma unroll
    for (int hb = 0; hb < 8; hb++)
        o[hb][0] = o[hb][1] = o[hb][2] = o[hb][3] = 0.0f;
    float lR = 0.0f, lR8 = 0.0f;

    if (ktbeg < ktend) {
        const uint32_t sb = (uint32_t)__cvta_generic_to_shared(sm);

        // K staging: 64 rows x 16 chunks (16B); V staging: 64 rows x 8 chunks
        const int kcrow = tid >> 4;          // 0..7 (+8i)
        const int kcq   = tid & 15;
        const int vcrow = tid >> 3;          // 0..15 (+16i)
        const int vch   = tid & 7;

        uint32_t qf[8][4];
        #pragma unroll
        for (int kb = 0; kb < 8; kb++) {
            float2 a0 = *(const float2*)&g_Q[base + (size_t)rowg  * HH + kb * 8 + 2 * c];
            float2 a1 = *(const float2*)&g_Q[base + (size_t)rowg8 * HH + kb * 8 + 2 * c];
            qf[kb][0] = __float_as_uint(a0.x);
            qf[kb][2] = __float_as_uint(a0.y);
            qf[kb][1] = __float_as_uint(a1.x);
            qf[kb][3] = __float_as_uint(a1.y);
        }

        auto issue = [&](int bf, int jb) {
            #pragma unroll
            for (int i = 0; i < 8; i++) {
                const int row = kcrow + i * 8;
                const uint32_t swz = (uint32_t)((kcq ^ ((row & 3) << 1)) << 4);
                cpa16(sb + (uint32_t)bf * 24576u + (uint32_t)row * 256u + swz,
                      &g_K[base + (size_t)(jb + row) * HH + kcq * 4]);
            }
            #pragma unroll
            for (int i = 0; i < 4; i++) {
                const int row = vcrow + i * 16;
                const uint32_t swz = (uint32_t)((vch ^ ((row & 3) << 1)) << 4);
                cpa16(sb + (uint32_t)bf * 24576u + 16384u + (uint32_t)row * 128u + swz,
                      g_Vth + (size_t)((b << 6) + row) * TT + jb + vch * 8);
            }
            cpa_commit();
        };

        issue(0, ktbeg * 64);

        int cur = 0;
        const int rx   = (r & 3) << 1;
        const int boff = 2 * (c & 1);
        const int cc   = c >> 1;

        for (int kt = ktbeg; kt < ktend; kt++) {
            const int jbase = kt * 64;
            cpa_wait0();
            __syncthreads();
            if (kt + 1 < ktend) issue(cur ^ 1, jbase + 64);

            const float*  kp = sm + cur * 6144;                    // 16 KB K
            const __half* vp = (const __half*)(sm + cur * 6144 + 4096);

            // ---- S = Q K^T (tf32, LDS.64 B-frags) ----
            float sS[8][4];
            #pragma unroll
            for (int nb = 0; nb < 8; nb++)
                sS[nb][0] = sS[nb][1] = sS[nb][2] = sS[nb][3] = 0.0f;
            #pragma unroll
            for (int nb = 0; nb < 8; nb++) {
                const float* rowp = kp + (nb * 8 + r) * 64;
                #pragma unroll
                for (int kb = 0; kb < 8; kb++) {
                    float2 t = *(const float2*)&rowp[(((2 * kb + cc) ^ rx) << 2) + boff];
                    mma_tf32(sS[nb], qf[kb],
                             __float_as_uint(t.x), __float_as_uint(t.y));
                }
            }

            if (kt == qt) {
                #pragma unroll
                for (int nb = 0; nb < 8; nb++) {
                    const int col = jbase + nb * 8 + 2 * c;
                    if (col     > rowg ) sS[nb][0] = -1.0e30f;
                    if (col + 1 > rowg ) sS[nb][1] = -1.0e30f;
                    if (col     > rowg8) sS[nb][2] = -1.0e30f;
                    if (col + 1 > rowg8) sS[nb][3] = -1.0e30f;
                }
            }

            // ---- fixed-max softmax: p = 2^(s - M) ----
            float sum0 = 0.0f, sum1 = 0.0f;
            #pragma unroll
            for (int nb = 0; nb < 8; nb++) {
                sS[nb][0] = ex2(sS[nb][0] - MCONST);
                sS[nb][1] = ex2(sS[nb][1] - MCONST);
                sS[nb][2] = ex2(sS[nb][2] - MCONST);
                sS[nb][3] = ex2(sS[nb][3] - MCONST);
                sum0 += sS[nb][0] + sS[nb][1];
                sum1 += sS[nb][2] + sS[nb][3];
            }
            lR  += sum0;
            lR8 += sum1;

            // ---- O += P @ V (fp16 m16n8k16; direct fragment reuse) ----
            #pragma unroll
            for (int kb = 0; kb < 4; kb++) {
                uint32_t a[4];
                a[0] = pack_h2(sS[2 * kb    ][0], sS[2 * kb    ][1]);
                a[1] = pack_h2(sS[2 * kb    ][2], sS[2 * kb    ][3]);
                a[2] = pack_h2(sS[2 * kb + 1][0], sS[2 * kb + 1][1]);
                a[3] = pack_h2(sS[2 * kb + 1][2], sS[2 * kb + 1][3]);
                #pragma unroll
                for (int hb = 0; hb < 8; hb++) {
                    const __half* vrow = vp + (hb * 8 + r) * 64;
                    uint2 bv = *(const uint2*)&vrow[(((2 * kb + cc) ^ rx) << 3) + (c & 1) * 4];
                    mma_f16(o[hb], a, bv.x, bv.y);
                }
            }
            cur ^= 1;
        }
    }

    lR  += __shfl_xor_sync(0xffffffffu, lR, 1);
    lR  += __shfl_xor_sync(0xffffffffu, lR, 2);
    lR8 += __shfl_xor_sync(0xffffffffu, lR8, 1);
    lR8 += __shfl_xor_sync(0xffffffffu, lR8, 2);

    const size_t pr  = (size_t)(s * BB + b) * TT + rowg;
    const size_t pr8 = pr + 8;
    #pragma unroll
    for (int hb = 0; hb < 8; hb++) {
        *(float2*)&g_pO[pr  * HH + hb * 8 + 2 * c] = make_float2(o[hb][0], o[hb][1]);
        *(float2*)&g_pO[pr8 * HH + hb * 8 + 2 * c] = make_float2(o[hb][2], o[hb][3]);
    }
    if (c == 0) {
        g_pl[pr]  = lR;
        g_pl[pr8] = lR8;
    }
}

// ---------------------------------------------------------------------------
// Kernel 3: merge the four kv-splits (unit weights: common fixed max).
// ---------------------------------------------------------------------------
__global__ __launch_bounds__(256) void combine_kernel(float* __restrict__ out)
{
    const int gid  = blockIdx.x * 256 + threadIdx.x;
    const int rowg = gid >> 4;
    const int col  = (gid & 15) * 4;

    float denom = 0.0f;
    #pragma unroll
    for (int sp = 0; sp < NSPLIT; sp++)
        denom += g_pl[sp * BT + rowg];
    const float inv = 1.0f / denom;

    float4 acc = make_float4(0.f, 0.f, 0.f, 0.f);
    #pragma unroll
    for (int sp = 0; sp < NSPLIT; sp++) {
        float4 O = *(const float4*)&g_pO[((size_t)sp * BT + rowg) * HH + col];
        acc.x += O.x;
        acc.y += O.y;
        acc.z += O.z;
        acc.w += O.w;
    }
    acc.x *= inv; acc.y *= inv; acc.z *= inv; acc.w *= inv;
    *(float4*)&out[(size_t)rowg * HH + col] = acc;
}

// ---------------------------------------------------------------------------
extern "C" void kernel_launch(void* const* d_in, const int* in_sizes, int n_in,
                              void* d_out, int out_size)
{
    const float* x  = (const float*)d_in[0];
    const float* Wq = (const float*)d_in[1];
    const float* Wk = (const float*)d_in[2];
    const float* Wv = (const float*)d_in[3];
    float* out = (float*)d_out;

    const int attn_smem = 2 * 24576;     // 48 KB (K fp32 16K + V fp16 8K, x2)
    cudaFuncSetAttribute(attn_kernel, cudaFuncAttributeMaxDynamicSharedMemorySize,
                         attn_smem);

    prep_w<<<(DD * 192 + 255) / 256, 256>>>(Wq, Wk, Wv);
    qkv_mma<<<(BT / 128) * 2, 256>>>(x);
    attn_kernel<<<64 * BB * NSPLIT, 128, attn_smem>>>();
    combine_kernel<<<(BT * HH / 4) / 256, 256>>>(out);
}

// round 14
// speedup vs baseline: 1.1851x; 1.0683x over previous
#include <cuda_runtime.h>
#include <cuda_fp16.h>
#include <cstdint>

#define BB 4
#define TT 4096
#define DD 768
#define HH 64
#define BT (BB*TT)
#define NSPLIT 4
#define MCONST 16.0f

// Scratch.
// g_Qh: fp16, pre-scaled (x0.125*log2e), h PAIR-PERMUTED.
// g_Kh: fp16, h PAIR-PERMUTED.
// g_Vth: fp16, transposed [b][h][t], t PAIR-PERMUTED.
// Pair permutation within each 16-elem group: pair p=4s+c -> position 2c+s,
// so fp16 MMA B/A fragment pairs (2c,2c+1) and (2c+8,2c+9) become adjacent
// -> one 8-byte load serves both k-halves of an m16n8k16 fragment.
__device__ __half g_Qh[BT * HH];
__device__ __half g_Kh[BT * HH];
__device__ __half g_Vth[BB * HH * TT];
__device__ float2 g_Wsp[DD * 192];
__device__ float  g_pO[NSPLIT * BT * HH];   // partial O (scale 2^-MCONST)
__device__ float  g_pl[NSPLIT * BT];        // partial denom (same scale)

// ---------------------------------------------------------------------------
// helpers
// ---------------------------------------------------------------------------
__device__ __forceinline__ uint32_t f2tf(float f) {
    uint32_t u;
    asm("cvt.rna.tf32.f32 %0, %1;" : "=r"(u) : "f"(f));
    return u;
}
__device__ __forceinline__ float tf32f(float f) {
    return __uint_as_float(f2tf(f));
}
__device__ __forceinline__ float ex2(float x) {
    float y;
    asm("ex2.approx.f32 %0, %1;" : "=f"(y) : "f"(x));
    return y;
}
// pack (lo, hi) floats -> f16x2 (lo in low half)
__device__ __forceinline__ uint32_t pack_h2(float lo, float hi) {
    uint32_t u;
    asm("cvt.rn.f16x2.f32 %0, %1, %2;" : "=r"(u) : "f"(hi), "f"(lo));
    return u;
}

__device__ __forceinline__ void mma_tf32(float d[4], const uint32_t a[4],
                                         uint32_t b0, uint32_t b1) {
    asm volatile(
        "mma.sync.aligned.m16n8k8.row.col.f32.tf32.tf32.f32 "
        "{%0,%1,%2,%3}, {%4,%5,%6,%7}, {%8,%9}, {%0,%1,%2,%3};"
        : "+f"(d[0]), "+f"(d[1]), "+f"(d[2]), "+f"(d[3])
        : "r"(a[0]), "r"(a[1]), "r"(a[2]), "r"(a[3]), "r"(b0), "r"(b1));
}

__device__ __forceinline__ void mma_f16(float d[4], const uint32_t a[4],
                                        uint32_t b0, uint32_t b1) {
    asm volatile(
        "mma.sync.aligned.m16n8k16.row.col.f32.f16.f16.f32 "
        "{%0,%1,%2,%3}, {%4,%5,%6,%7}, {%8,%9}, {%0,%1,%2,%3};"
        : "+f"(d[0]), "+f"(d[1]), "+f"(d[2]), "+f"(d[3])
        : "r"(a[0]), "r"(a[1]), "r"(a[2]), "r"(a[3]), "r"(b0), "r"(b1));
}

__device__ __forceinline__ void cpa16(uint32_t smem_dst, const void* gsrc) {
    asm volatile("cp.async.cg.shared.global [%0], [%1], 16;"
                 :: "r"(smem_dst), "l"(gsrc));
}
__device__ __forceinline__ void cpa_commit() {
    asm volatile("cp.async.commit_group;");
}
__device__ __forceinline__ void cpa_wait0() {
    asm volatile("cp.async.wait_group 0;" ::: "memory");
}

// pair-permuted position for even column `col` within its 16-group
__device__ __forceinline__ int pairperm(int col) {
    const int pg = (col >> 1) & 7;               // pair index in group
    const int np = ((pg & 3) << 1) | (pg >> 2);  // 4s+c -> 2c+s
    return (col & ~15) | (np << 1);
}

// ---------------------------------------------------------------------------
// Kernel 0: split W = [Wq|Wk|Wv] into (hi, lo) tf32 pair.
// ---------------------------------------------------------------------------
__global__ __launch_bounds__(256) void prep_w(
    const float* __restrict__ Wq, const float* __restrict__ Wk,
    const float* __restrict__ Wv)
{
    int i = blockIdx.x * 256 + threadIdx.x;
    if (i >= DD * 192) return;
    int k = i / 192, n = i % 192;
    float v = (n < 64) ? Wq[k * 64 + n]
            : (n < 128) ? Wk[k * 64 + n - 64]
            : Wv[k * 64 + n - 128];
    float hi = tf32f(v);
    float lo = tf32f(v - hi);
    g_Wsp[i] = make_float2(hi, lo);
}

// ---------------------------------------------------------------------------
// Kernel 1: QKV projection (R11 two-block shape), 3-term tf32 split.
// Epilogue: Q fp16 scaled + pair-permuted h; K fp16 pair-permuted h;
// V fp16 transposed [b][h][t] with pair-permuted t.
// ---------------------------------------------------------------------------
#define QSCALE (0.125f * 1.4426950408889634f)

__global__ __launch_bounds__(256) void qkv_mma(const float* __restrict__ x)
{
    __shared__ float  xs[128 * 36];
    __shared__ float4 wf[4 * 12 * 33];

    const int tid = threadIdx.x;
    const int w   = tid >> 5;
    const int l   = tid & 31;
    const int mg  = w >> 1;
    const int ng  = w & 1;
    const int row0 = (blockIdx.x >> 1) * 128;
    const int n0   = (blockIdx.x & 1) * 96;

    float acc[2][6][4];
    #pragma unroll
    for (int mt = 0; mt < 2; mt++)
        #pragma unroll
        for (int nb = 0; nb < 6; nb++)
            acc[mt][nb][0] = acc[mt][nb][1] = acc[mt][nb][2] = acc[mt][nb][3] = 0.0f;

    float4 px[4];
    float2 pw[12];

    #pragma unroll
    for (int t = 0; t < 4; t++) {
        int f  = tid + t * 256;
        int r  = f >> 3;
        int c4 = (f & 7) * 4;
        px[t] = *(const float4*)&x[(size_t)(row0 + r) * DD + c4];
    }
    #pragma unroll
    for (int t = 0; t < 12; t++) {
        int i  = tid + t * 256;
        int kk = i / 96;
        int nn = i % 96;
        pw[t] = g_Wsp[(size_t)kk * 192 + n0 + nn];
    }

    for (int k0 = 0; k0 < DD; k0 += 32) {
        #pragma unroll
        for (int t = 0; t < 4; t++) {
            int f  = tid + t * 256;
            int r  = f >> 3;
            int c4 = (f & 7) * 4;
            *(float4*)&xs[r * 36 + c4] = px[t];
        }
        #pragma unroll
        for (int t = 0; t < 12; t++) {
            int i  = tid + t * 256;
            int kk = i / 96;
            int nn = i % 96;
            int kb   = kk >> 3, kr = kk & 7;
            int slot = kr >> 2;
            int nb   = nn >> 3;
            int lane = ((nn & 7) << 2) | (kr & 3);
            float* p = (float*)&wf[(kb * 12 + nb) * 33 + lane];
            p[slot]     = pw[t].x;
            p[2 + slot] = pw[t].y;
        }
        __syncthreads();

        if (k0 + 32 < DD) {
            #pragma unroll
            for (int t = 0; t < 4; t++) {
                int f  = tid + t * 256;
                int r  = f >> 3;
                int c4 = (f & 7) * 4;
                px[t] = *(const float4*)&x[(size_t)(row0 + r) * DD + k0 + 32 + c4];
            }
            #pragma unroll
            for (int t = 0; t < 12; t++) {
                int i  = tid + t * 256;
                int kk = i / 96;
                int nn = i % 96;
                pw[t] = g_Wsp[(size_t)(k0 + 32 + kk) * 192 + n0 + nn];
            }
        }

        #pragma unroll
        for (int kb = 0; kb < 4; kb++) {
            uint32_t ahi[2][4], alo[2][4];
            #pragma unroll
            for (int mt = 0; mt < 2; mt++) {
                const int rA = mg * 32 + mt * 16 + (l >> 2);
                const int cA = kb * 8 + (l & 3);
                float a0 = xs[rA * 36 + cA];
                float a1 = xs[(rA + 8) * 36 + cA];
                float a2 = xs[rA * 36 + cA + 4];
                float a3 = xs[(rA + 8) * 36 + cA + 4];
                ahi[mt][0] = f2tf(a0); alo[mt][0] = f2tf(a0 - __uint_as_float(ahi[mt][0]));
                ahi[mt][1] = f2tf(a1); alo[mt][1] = f2tf(a1 - __uint_as_float(ahi[mt][1]));
                ahi[mt][2] = f2tf(a2); alo[mt][2] = f2tf(a2 - __uint_as_float(ahi[mt][2]));
                ahi[mt][3] = f2tf(a3); alo[mt][3] = f2tf(a3 - __uint_as_float(ahi[mt][3]));
            }
            #pragma unroll
            for (int nb = 0; nb < 6; nb++) {
                float4 q = wf[(kb * 12 + ng * 6 + nb) * 33 + l];
                uint32_t bh0 = __float_as_uint(q.x), bh1 = __float_as_uint(q.y);
                uint32_t bl0 = __float_as_uint(q.z), bl1 = __float_as_uint(q.w);
                #pragma unroll
                for (int mt = 0; mt < 2; mt++) {
                    mma_tf32(acc[mt][nb], ahi[mt], bh0, bh1);
                    mma_tf32(acc[mt][nb], ahi[mt], bl0, bl1);
                    mma_tf32(acc[mt][nb], alo[mt], bh0, bh1);
                }
            }
        }
        __syncthreads();
    }

    #pragma unroll
    for (int mt = 0; mt < 2; mt++) {
        #pragma unroll
        for (int nb = 0; nb < 6; nb++) {
            const int rowa  = row0 + mg * 32 + mt * 16 + (l >> 2);
            const int nglob = n0 + ng * 48 + nb * 8 + (l & 3) * 2;
            const int mat   = nglob >> 6;
            const int col   = nglob & 63;
            if (mat == 0) {
                const int pos = pairperm(col);
                g_Qh[(size_t)rowa * HH + pos]           = __float2half_rn(QSCALE * acc[mt][nb][0]);
                g_Qh[(size_t)rowa * HH + pos + 1]       = __float2half_rn(QSCALE * acc[mt][nb][1]);
                g_Qh[(size_t)(rowa + 8) * HH + pos]     = __float2half_rn(QSCALE * acc[mt][nb][2]);
                g_Qh[(size_t)(rowa + 8) * HH + pos + 1] = __float2half_rn(QSCALE * acc[mt][nb][3]);
            } else if (mat == 1) {
                const int pos = pairperm(col);
                g_Kh[(size_t)rowa * HH + pos]           = __float2half_rn(acc[mt][nb][0]);
                g_Kh[(size_t)rowa * HH + pos + 1]       = __float2half_rn(acc[mt][nb][1]);
                g_Kh[(size_t)(rowa + 8) * HH + pos]     = __float2half_rn(acc[mt][nb][2]);
                g_Kh[(size_t)(rowa + 8) * HH + pos + 1] = __float2half_rn(acc[mt][nb][3]);
            } else {
                // V fp16, transposed [b][h][t], pair-permuted t.
                const int bb = rowa >> 12;
                const int t0 = rowa & 4095;
                const int q2 = (t0 >> 1) & 3;
                const int tp = (t0 & ~15) | (q2 << 2) | (t0 & 1);
                __half* v0 = g_Vth + (size_t)((bb << 6) + col) * TT;
                __half* v1 = g_Vth + (size_t)((bb << 6) + col + 1) * TT;
                v0[tp]     = __float2half_rn(acc[mt][nb][0]);
                v1[tp]     = __float2half_rn(acc[mt][nb][1]);
                v0[tp + 2] = __float2half_rn(acc[mt][nb][2]);
                v1[tp + 2] = __float2half_rn(acc[mt][nb][3]);
            }
        }
    }
}

// ---------------------------------------------------------------------------
// Kernel 2: causal flash attention, split-kv (4), fixed-max softmax.
// BOTH GEMMs fp16 m16n8k16 (fp32 accumulate). K/V tiles fp16 in smem
// (8 KB each, 32 KB total double-buffered). Q fragments: 16 regs via LDG.64.
// B-fragments: single LDS.64 each (pair-permuted storage, chunk-XOR swizzle).
// ---------------------------------------------------------------------------
__global__ __launch_bounds__(128, 4) void attn_kernel()
{
    extern __shared__ __half smh[];   // [buf][K 4096 | V 4096] halves

    const int tid = threadIdx.x;
    const int w   = tid >> 5;
    const int l   = tid & 31;
    const int r   = l >> 2;
    const int c   = l & 3;

    const int bid = blockIdx.x;
    const int qt  = 63 - (bid >> 4);
    const int b   = (bid >> 2) & 3;
    const int s   = bid & 3;
    const int q0  = qt * 64;
    const size_t base = (size_t)b * TT * HH;

    const int nt    = qt + 1;
    const int chunk = (nt + NSPLIT - 1) >> 2;
    const int ktbeg = min(s * chunk, nt);
    const int ktend = min(ktbeg + chunk, nt);

    const int rowg  = q0 + w * 16 + r;
    const int rowg8 = rowg + 8;

    float o[8][4];
    #pragma unroll
    for (int hb = 0; hb < 8; hb++)
        o[hb][0] = o[hb][1] = o[hb][2] = o[hb][3] = 0.0f;
    float lR = 0.0f, lR8 = 0.0f;

    if (ktbeg < ktend) {
        const uint32_t sb = (uint32_t)__cvta_generic_to_shared(smh);

        // staging: 64 rows x 8 chunks (16B) per tensor -> 4 chunks/thread each
        const int crow = tid >> 3;           // 0..15 (+16i)
        const int ch   = tid & 7;

        // Q fragments fp16: 4 k16 chunks x 4 f16x2 regs
        uint32_t qf[4][4];
        #pragma unroll
        for (int kb = 0; kb < 4; kb++) {
            uint2 u0 = *(const uint2*)&g_Qh[base + (size_t)rowg  * HH + kb * 16 + 4 * c];
            uint2 u1 = *(const uint2*)&g_Qh[base + (size_t)rowg8 * HH + kb * 16 + 4 * c];
            qf[kb][0] = u0.x;   // row r,   k pair 2c
            qf[kb][1] = u1.x;   // row r+8, k pair 2c
            qf[kb][2] = u0.y;   // row r,   k pair 2c+8
            qf[kb][3] = u1.y;   // row r+8, k pair 2c+8
        }

        auto issue = [&](int bf, int jb) {
            #pragma unroll
            for (int i = 0; i < 4; i++) {
                const int row = crow + i * 16;
                const uint32_t swz = (uint32_t)((ch ^ ((row & 3) << 1)) << 4);
                cpa16(sb + (uint32_t)bf * 16384u + (uint32_t)row * 128u + swz,
                      g_Kh + base + (size_t)(jb + row) * HH + ch * 8);
                cpa16(sb + (uint32_t)bf * 16384u + 8192u + (uint32_t)row * 128u + swz,
                      g_Vth + (size_t)((b << 6) + row) * TT + jb + ch * 8);
            }
            cpa_commit();
        };

        issue(0, ktbeg * 64);

        int cur = 0;
        const int rx   = (r & 3) << 1;
        const int cc   = c >> 1;
        const int hoff = (c & 1) * 4;        // halves offset within chunk

        for (int kt = ktbeg; kt < ktend; kt++) {
            const int jbase = kt * 64;
            cpa_wait0();
            __syncthreads();
            if (kt + 1 < ktend) issue(cur ^ 1, jbase + 64);

            const __half* kp = smh + cur * 8192;
            const __half* vp = kp + 4096;

            // ---- S = Q K^T (fp16 m16n8k16) ----
            float sS[8][4];
            #pragma unroll
            for (int nb = 0; nb < 8; nb++)
                sS[nb][0] = sS[nb][1] = sS[nb][2] = sS[nb][3] = 0.0f;
            #pragma unroll
            for (int nb = 0; nb < 8; nb++) {
                const __half* krow = kp + (nb * 8 + r) * 64;
                #pragma unroll
                for (int kb = 0; kb < 4; kb++) {
                    uint2 bk = *(const uint2*)&krow[(((2 * kb + cc) ^ rx) << 3) + hoff];
                    mma_f16(sS[nb], qf[kb], bk.x, bk.y);
                }
            }

            if (kt == qt) {
                #pragma unroll
                for (int nb = 0; nb < 8; nb++) {
                    const int col = jbase + nb * 8 + 2 * c;
                    if (col     > rowg ) sS[nb][0] = -1.0e30f;
                    if (col + 1 > rowg ) sS[nb][1] = -1.0e30f;
                    if (col     > rowg8) sS[nb][2] = -1.0e30f;
                    if (col + 1 > rowg8) sS[nb][3] = -1.0e30f;
                }
            }

            // ---- fixed-max softmax: p = 2^(s - M) ----
            float sum0 = 0.0f, sum1 = 0.0f;
            #pragma unroll
            for (int nb = 0; nb < 8; nb++) {
                sS[nb][0] = ex2(sS[nb][0] - MCONST);
                sS[nb][1] = ex2(sS[nb][1] - MCONST);
                sS[nb][2] = ex2(sS[nb][2] - MCONST);
                sS[nb][3] = ex2(sS[nb][3] - MCONST);
                sum0 += sS[nb][0] + sS[nb][1];
                sum1 += sS[nb][2] + sS[nb][3];
            }
            lR  += sum0;
            lR8 += sum1;

            // ---- O += P @ V (fp16 m16n8k16; direct fragment reuse) ----
            #pragma unroll
            for (int kb = 0; kb < 4; kb++) {
                uint32_t a[4];
                a[0] = pack_h2(sS[2 * kb    ][0], sS[2 * kb    ][1]);
                a[1] = pack_h2(sS[2 * kb    ][2], sS[2 * kb    ][3]);
                a[2] = pack_h2(sS[2 * kb + 1][0], sS[2 * kb + 1][1]);
                a[3] = pack_h2(sS[2 * kb + 1][2], sS[2 * kb + 1][3]);
                #pragma unroll
                for (int hb = 0; hb < 8; hb++) {
                    const __half* vrow = vp + (hb * 8 + r) * 64;
                    uint2 bv = *(const uint2*)&vrow[(((2 * kb + cc) ^ rx) << 3) + hoff];
                    mma_f16(o[hb], a, bv.x, bv.y);
                }
            }
            cur ^= 1;
        }
    }

    lR  += __shfl_xor_sync(0xffffffffu, lR, 1);
    lR  += __shfl_xor_sync(0xffffffffu, lR, 2);
    lR8 += __shfl_xor_sync(0xffffffffu, lR8, 1);
    lR8 += __shfl_xor_sync(0xffffffffu, lR8, 2);

    const size_t pr  = (size_t)(s * BB + b) * TT + rowg;
    const size_t pr8 = pr + 8;
    #pragma unroll
    for (int hb = 0; hb < 8; hb++) {
        *(float2*)&g_pO[pr  * HH + hb * 8 + 2 * c] = make_float2(o[hb][0], o[hb][1]);
        *(float2*)&g_pO[pr8 * HH + hb * 8 + 2 * c] = make_float2(o[hb][2], o[hb][3]);
    }
    if (c == 0) {
        g_pl[pr]  = lR;
        g_pl[pr8] = lR8;
    }
}

// ---------------------------------------------------------------------------
// Kernel 3: merge the four kv-splits (unit weights: common fixed max).
// ---------------------------------------------------------------------------
__global__ __launch_bounds__(256) void combine_kernel(float* __restrict__ out)
{
    const int gid  = blockIdx.x * 256 + threadIdx.x;
    const int rowg = gid >> 4;
    const int col  = (gid & 15) * 4;

    float denom = 0.0f;
    #pragma unroll
    for (int sp = 0; sp < NSPLIT; sp++)
        denom += g_pl[sp * BT + rowg];
    const float inv = 1.0f / denom;

    float4 acc = make_float4(0.f, 0.f, 0.f, 0.f);
    #pragma unroll
    for (int sp = 0; sp < NSPLIT; sp++) {
        float4 O = *(const float4*)&g_pO[((size_t)sp * BT + rowg) * HH + col];
        acc.x += O.x;
        acc.y += O.y;
        acc.z += O.z;
        acc.w += O.w;
    }
    acc.x *= inv; acc.y *= inv; acc.z *= inv; acc.w *= inv;
    *(float4*)&out[(size_t)rowg * HH + col] = acc;
}

// ---------------------------------------------------------------------------
extern "C" void kernel_launch(void* const* d_in, const int* in_sizes, int n_in,
                              void* d_out, int out_size)
{
    const float* x  = (const float*)d_in[0];
    const float* Wq = (const float*)d_in[1];
    const float* Wk = (const float*)d_in[2];
    const float* Wv = (const float*)d_in[3];
    float* out = (float*)d_out;

    const int attn_smem = 2 * 16384;     // 32 KB (K fp16 8K + V fp16 8K, x2)
    cudaFuncSetAttribute(attn_kernel, cudaFuncAttributeMaxDynamicSharedMemorySize,
                         attn_smem);

    prep_w<<<(DD * 192 + 255) / 256, 256>>>(Wq, Wk, Wv);
    qkv_mma<<<(BT / 128) * 2, 256>>>(x);
    attn_kernel<<<64 * BB * NSPLIT, 128, attn_smem>>>();
    combine_kernel<<<(BT * HH / 4) / 256, 256>>>(out);
}

// round 15
// speedup vs baseline: 1.3631x; 1.1502x over previous
#include <cuda_runtime.h>
#include <cuda_fp16.h>
#include <cstdint>

#define BB 4
#define TT 4096
#define DD 768
#define HH 64
#define BT (BB*TT)
#define NSPLIT 4
#define MCONST 16.0f

// Scratch.
// g_Qh: fp16, pre-scaled (x0.125*log2e), h PAIR-PERMUTED.
// g_Kh: fp16, h PAIR-PERMUTED.
// g_Vth: fp16, transposed [b][h][t], t PAIR-PERMUTED.
__device__ __half g_Qh[BT * HH];
__device__ __half g_Kh[BT * HH];
__device__ __half g_Vth[BB * HH * TT];
__device__ float2 g_Wsp[DD * 192];
__device__ float  g_pO[NSPLIT * BT * HH];   // partial O (scale 2^-MCONST)
__device__ float  g_pl[NSPLIT * BT];        // partial denom (same scale)

// ---------------------------------------------------------------------------
// helpers
// ---------------------------------------------------------------------------
__device__ __forceinline__ uint32_t f2tf(float f) {
    uint32_t u;
    asm("cvt.rna.tf32.f32 %0, %1;" : "=r"(u) : "f"(f));
    return u;
}
__device__ __forceinline__ float tf32f(float f) {
    return __uint_as_float(f2tf(f));
}
__device__ __forceinline__ float ex2(float x) {
    float y;
    asm("ex2.approx.f32 %0, %1;" : "=f"(y) : "f"(x));
    return y;
}
__device__ __forceinline__ uint32_t pack_h2(float lo, float hi) {
    uint32_t u;
    asm("cvt.rn.f16x2.f32 %0, %1, %2;" : "=r"(u) : "f"(hi), "f"(lo));
    return u;
}

__device__ __forceinline__ void mma_tf32(float d[4], const uint32_t a[4],
                                         uint32_t b0, uint32_t b1) {
    asm volatile(
        "mma.sync.aligned.m16n8k8.row.col.f32.tf32.tf32.f32 "
        "{%0,%1,%2,%3}, {%4,%5,%6,%7}, {%8,%9}, {%0,%1,%2,%3};"
        : "+f"(d[0]), "+f"(d[1]), "+f"(d[2]), "+f"(d[3])
        : "r"(a[0]), "r"(a[1]), "r"(a[2]), "r"(a[3]), "r"(b0), "r"(b1));
}

__device__ __forceinline__ void mma_f16(float d[4], const uint32_t a[4],
                                        uint32_t b0, uint32_t b1) {
    asm volatile(
        "mma.sync.aligned.m16n8k16.row.col.f32.f16.f16.f32 "
        "{%0,%1,%2,%3}, {%4,%5,%6,%7}, {%8,%9}, {%0,%1,%2,%3};"
        : "+f"(d[0]), "+f"(d[1]), "+f"(d[2]), "+f"(d[3])
        : "r"(a[0]), "r"(a[1]), "r"(a[2]), "r"(a[3]), "r"(b0), "r"(b1));
}

__device__ __forceinline__ void cpa16(uint32_t smem_dst, const void* gsrc) {
    asm volatile("cp.async.cg.shared.global [%0], [%1], 16;"
                 :: "r"(smem_dst), "l"(gsrc));
}
__device__ __forceinline__ void cpa_commit() {
    asm volatile("cp.async.commit_group;");
}
__device__ __forceinline__ void cpa_wait0() {
    asm volatile("cp.async.wait_group 0;" ::: "memory");
}
__device__ __forceinline__ void cpa_wait1() {
    asm volatile("cp.async.wait_group 1;" ::: "memory");
}

// pair-permuted position for even column `col` within its 16-group
__device__ __forceinline__ int pairperm(int col) {
    const int pg = (col >> 1) & 7;
    const int np = ((pg & 3) << 1) | (pg >> 2);
    return (col & ~15) | (np << 1);
}

// ---------------------------------------------------------------------------
// Kernel 0: split W = [Wq|Wk|Wv] into (hi, lo) tf32 pair.
// ---------------------------------------------------------------------------
__global__ __launch_bounds__(256) void prep_w(
    const float* __restrict__ Wq, const float* __restrict__ Wk,
    const float* __restrict__ Wv)
{
    int i = blockIdx.x * 256 + threadIdx.x;
    if (i >= DD * 192) return;
    int k = i / 192, n = i % 192;
    float v = (n < 64) ? Wq[k * 64 + n]
            : (n < 128) ? Wk[k * 64 + n - 64]
            : Wv[k * 64 + n - 128];
    float hi = tf32f(v);
    float lo = tf32f(v - hi);
    g_Wsp[i] = make_float2(hi, lo);
}

// ---------------------------------------------------------------------------
// Kernel 1: QKV projection, 2-TERM tf32 split (ahi*bhi + ahi*blo).
// Epilogue: Q fp16 scaled + pair-permuted h; K fp16 pair-permuted h;
// V fp16 transposed [b][h][t] with pair-permuted t.
// ---------------------------------------------------------------------------
#define QSCALE (0.125f * 1.4426950408889634f)

__global__ __launch_bounds__(256) void qkv_mma(const float* __restrict__ x)
{
    __shared__ float  xs[128 * 36];
    __shared__ float4 wf[4 * 12 * 33];

    const int tid = threadIdx.x;
    const int w   = tid >> 5;
    const int l   = tid & 31;
    const int mg  = w >> 1;
    const int ng  = w & 1;
    const int row0 = (blockIdx.x >> 1) * 128;
    const int n0   = (blockIdx.x & 1) * 96;

    float acc[2][6][4];
    #pragma unroll
    for (int mt = 0; mt < 2; mt++)
        #pragma unroll
        for (int nb = 0; nb < 6; nb++)
            acc[mt][nb][0] = acc[mt][nb][1] = acc[mt][nb][2] = acc[mt][nb][3] = 0.0f;

    float4 px[4];
    float2 pw[12];

    #pragma unroll
    for (int t = 0; t < 4; t++) {
        int f  = tid + t * 256;
        int r  = f >> 3;
        int c4 = (f & 7) * 4;
        px[t] = *(const float4*)&x[(size_t)(row0 + r) * DD + c4];
    }
    #pragma unroll
    for (int t = 0; t < 12; t++) {
        int i  = tid + t * 256;
        int kk = i / 96;
        int nn = i % 96;
        pw[t] = g_Wsp[(size_t)kk * 192 + n0 + nn];
    }

    for (int k0 = 0; k0 < DD; k0 += 32) {
        #pragma unroll
        for (int t = 0; t < 4; t++) {
            int f  = tid + t * 256;
            int r  = f >> 3;
            int c4 = (f & 7) * 4;
            *(float4*)&xs[r * 36 + c4] = px[t];
        }
        #pragma unroll
        for (int t = 0; t < 12; t++) {
            int i  = tid + t * 256;
            int kk = i / 96;
            int nn = i % 96;
            int kb   = kk >> 3, kr = kk & 7;
            int slot = kr >> 2;
            int nb   = nn >> 3;
            int lane = ((nn & 7) << 2) | (kr & 3);
            float* p = (float*)&wf[(kb * 12 + nb) * 33 + lane];
            p[slot]     = pw[t].x;
            p[2 + slot] = pw[t].y;
        }
        __syncthreads();

        if (k0 + 32 < DD) {
            #pragma unroll
            for (int t = 0; t < 4; t++) {
                int f  = tid + t * 256;
                int r  = f >> 3;
                int c4 = (f & 7) * 4;
                px[t] = *(const float4*)&x[(size_t)(row0 + r) * DD + k0 + 32 + c4];
            }
            #pragma unroll
            for (int t = 0; t < 12; t++) {
                int i  = tid + t * 256;
                int kk = i / 96;
                int nn = i % 96;
                pw[t] = g_Wsp[(size_t)(k0 + 32 + kk) * 192 + n0 + nn];
            }
        }

        #pragma unroll
        for (int kb = 0; kb < 4; kb++) {
            uint32_t ahi[2][4];
            #pragma unroll
            for (int mt = 0; mt < 2; mt++) {
                const int rA = mg * 32 + mt * 16 + (l >> 2);
                const int cA = kb * 8 + (l & 3);
                ahi[mt][0] = f2tf(xs[rA * 36 + cA]);
                ahi[mt][1] = f2tf(xs[(rA + 8) * 36 + cA]);
                ahi[mt][2] = f2tf(xs[rA * 36 + cA + 4]);
                ahi[mt][3] = f2tf(xs[(rA + 8) * 36 + cA + 4]);
            }
            #pragma unroll
            for (int nb = 0; nb < 6; nb++) {
                float4 q = wf[(kb * 12 + ng * 6 + nb) * 33 + l];
                uint32_t bh0 = __float_as_uint(q.x), bh1 = __float_as_uint(q.y);
                uint32_t bl0 = __float_as_uint(q.z), bl1 = __float_as_uint(q.w);
                #pragma unroll
                for (int mt = 0; mt < 2; mt++) {
                    mma_tf32(acc[mt][nb], ahi[mt], bh0, bh1);
                    mma_tf32(acc[mt][nb], ahi[mt], bl0, bl1);
                }
            }
        }
        __syncthreads();
    }

    #pragma unroll
    for (int mt = 0; mt < 2; mt++) {
        #pragma unroll
        for (int nb = 0; nb < 6; nb++) {
            const int rowa  = row0 + mg * 32 + mt * 16 + (l >> 2);
            const int nglob = n0 + ng * 48 + nb * 8 + (l & 3) * 2;
            const int mat   = nglob >> 6;
            const int col   = nglob & 63;
            if (mat == 0) {
                const int pos = pairperm(col);
                g_Qh[(size_t)rowa * HH + pos]           = __float2half_rn(QSCALE * acc[mt][nb][0]);
                g_Qh[(size_t)rowa * HH + pos + 1]       = __float2half_rn(QSCALE * acc[mt][nb][1]);
                g_Qh[(size_t)(rowa + 8) * HH + pos]     = __float2half_rn(QSCALE * acc[mt][nb][2]);
                g_Qh[(size_t)(rowa + 8) * HH + pos + 1] = __float2half_rn(QSCALE * acc[mt][nb][3]);
            } else if (mat == 1) {
                const int pos = pairperm(col);
                g_Kh[(size_t)rowa * HH + pos]           = __float2half_rn(acc[mt][nb][0]);
                g_Kh[(size_t)rowa * HH + pos + 1]       = __float2half_rn(acc[mt][nb][1]);
                g_Kh[(size_t)(rowa + 8) * HH + pos]     = __float2half_rn(acc[mt][nb][2]);
                g_Kh[(size_t)(rowa + 8) * HH + pos + 1] = __float2half_rn(acc[mt][nb][3]);
            } else {
                const int bb = rowa >> 12;
                const int t0 = rowa & 4095;
                const int q2 = (t0 >> 1) & 3;
                const int tp = (t0 & ~15) | (q2 << 2) | (t0 & 1);
                __half* v0 = g_Vth + (size_t)((bb << 6) + col) * TT;
                __half* v1 = g_Vth + (size_t)((bb << 6) + col + 1) * TT;
                v0[tp]     = __float2half_rn(acc[mt][nb][0]);
                v1[tp]     = __float2half_rn(acc[mt][nb][1]);
                v0[tp + 2] = __float2half_rn(acc[mt][nb][2]);
                v1[tp + 2] = __float2half_rn(acc[mt][nb][3]);
            }
        }
    }
}

// ---------------------------------------------------------------------------
// Kernel 2: causal flash attention, split-kv (4), fixed-max softmax,
// fp16 MMAs both GEMMs, THREE-STAGE cp.async pipeline (two loads in flight).
// 3 x 16 KB buffers = 48 KB -> 4 CTAs/SM.
// ---------------------------------------------------------------------------
__global__ __launch_bounds__(128, 4) void attn_kernel()
{
    extern __shared__ __half smh[];   // [3 bufs][K 4096 | V 4096] halves

    const int tid = threadIdx.x;
    const int w   = tid >> 5;
    const int l   = tid & 31;
    const int r   = l >> 2;
    const int c   = l & 3;

    const int bid = blockIdx.x;
    const int qt  = 63 - (bid >> 4);
    const int b   = (bid >> 2) & 3;
    const int s   = bid & 3;
    const int q0  = qt * 64;
    const size_t base = (size_t)b * TT * HH;

    const int nt    = qt + 1;
    const int chunk = (nt + NSPLIT - 1) >> 2;
    const int ktbeg = min(s * chunk, nt);
    const int ktend = min(ktbeg + chunk, nt);

    const int rowg  = q0 + w * 16 + r;
    const int rowg8 = rowg + 8;

    float o[8][4];
    #pragma unroll
    for (int hb = 0; hb < 8; hb++)
        o[hb][0] = o[hb][1] = o[hb][2] = o[hb][3] = 0.0f;
    float lR = 0.0f, lR8 = 0.0f;

    if (ktbeg < ktend) {
        const uint32_t sb = (uint32_t)__cvta_generic_to_shared(smh);

        const int crow = tid >> 3;           // 0..15 (+16i)
        const int ch   = tid & 7;

        uint32_t qf[4][4];
        #pragma unroll
        for (int kb = 0; kb < 4; kb++) {
            uint2 u0 = *(const uint2*)&g_Qh[base + (size_t)rowg  * HH + kb * 16 + 4 * c];
            uint2 u1 = *(const uint2*)&g_Qh[base + (size_t)rowg8 * HH + kb * 16 + 4 * c];
            qf[kb][0] = u0.x;
            qf[kb][1] = u1.x;
            qf[kb][2] = u0.y;
            qf[kb][3] = u1.y;
        }

        auto issue = [&](int bf, int jb) {
            #pragma unroll
            for (int i = 0; i < 4; i++) {
                const int row = crow + i * 16;
                const uint32_t swz = (uint32_t)((ch ^ ((row & 3) << 1)) << 4);
                cpa16(sb + (uint32_t)bf * 16384u + (uint32_t)row * 128u + swz,
                      g_Kh + base + (size_t)(jb + row) * HH + ch * 8);
                cpa16(sb + (uint32_t)bf * 16384u + 8192u + (uint32_t)row * 128u + swz,
                      g_Vth + (size_t)((b << 6) + row) * TT + jb + ch * 8);
            }
            cpa_commit();
        };

        // prologue: two tiles in flight
        issue(0, ktbeg * 64);
        if (ktbeg + 1 < ktend) issue(1, (ktbeg + 1) * 64);

        int bi = 0;
        const int rx   = (r & 3) << 1;
        const int cc   = c >> 1;
        const int hoff = (c & 1) * 4;

        for (int kt = ktbeg; kt < ktend; kt++) {
            const int jbase = kt * 64;
            if (kt + 1 < ktend) cpa_wait1();   // tile kt done, kt+1 in flight
            else                cpa_wait0();   // only tile kt pending
            __syncthreads();                   // all warps done with tile kt-1
            if (kt + 2 < ktend) {
                int nb2 = bi + 2; if (nb2 >= 3) nb2 -= 3;
                issue(nb2, (kt + 2) * 64);     // overwrites tile kt-1's buffer
            }

            const __half* kp = smh + bi * 8192;
            const __half* vp = kp + 4096;

            // ---- S = Q K^T (fp16 m16n8k16) ----
            float sS[8][4];
            #pragma unroll
            for (int nb = 0; nb < 8; nb++)
                sS[nb][0] = sS[nb][1] = sS[nb][2] = sS[nb][3] = 0.0f;
            #pragma unroll
            for (int nb = 0; nb < 8; nb++) {
                const __half* krow = kp + (nb * 8 + r) * 64;
                #pragma unroll
                for (int kb = 0; kb < 4; kb++) {
                    uint2 bk = *(const uint2*)&krow[(((2 * kb + cc) ^ rx) << 3) + hoff];
                    mma_f16(sS[nb], qf[kb], bk.x, bk.y);
                }
            }

            if (kt == qt) {
                #pragma unroll
                for (int nb = 0; nb < 8; nb++) {
                    const int col = jbase + nb * 8 + 2 * c;
                    if (col     > rowg ) sS[nb][0] = -1.0e30f;
                    if (col + 1 > rowg ) sS[nb][1] = -1.0e30f;
                    if (col     > rowg8) sS[nb][2] = -1.0e30f;
                    if (col + 1 > rowg8) sS[nb][3] = -1.0e30f;
                }
            }

            // ---- fixed-max softmax: p = 2^(s - M) ----
            float sum0 = 0.0f, sum1 = 0.0f;
            #pragma unroll
            for (int nb = 0; nb < 8; nb++) {
                sS[nb][0] = ex2(sS[nb][0] - MCONST);
                sS[nb][1] = ex2(sS[nb][1] - MCONST);
                sS[nb][2] = ex2(sS[nb][2] - MCONST);
                sS[nb][3] = ex2(sS[nb][3] - MCONST);
                sum0 += sS[nb][0] + sS[nb][1];
                sum1 += sS[nb][2] + sS[nb][3];
            }
            lR  += sum0;
            lR8 += sum1;

            // ---- O += P @ V (fp16; direct fragment reuse) ----
            #pragma unroll
            for (int kb = 0; kb < 4; kb++) {
                uint32_t a[4];
                a[0] = pack_h2(sS[2 * kb    ][0], sS[2 * kb    ][1]);
                a[1] = pack_h2(sS[2 * kb    ][2], sS[2 * kb    ][3]);
                a[2] = pack_h2(sS[2 * kb + 1][0], sS[2 * kb + 1][1]);
                a[3] = pack_h2(sS[2 * kb + 1][2], sS[2 * kb + 1][3]);
                #pragma unroll
                for (int hb = 0; hb < 8; hb++) {
                    const __half* vrow = vp + (hb * 8 + r) * 64;
                    uint2 bv = *(const uint2*)&vrow[(((2 * kb + cc) ^ rx) << 3) + hoff];
                    mma_f16(o[hb], a, bv.x, bv.y);
                }
            }
            bi = (bi == 2) ? 0 : bi + 1;
        }
    }

    lR  += __shfl_xor_sync(0xffffffffu, lR, 1);
    lR  += __shfl_xor_sync(0xffffffffu, lR, 2);
    lR8 += __shfl_xor_sync(0xffffffffu, lR8, 1);
    lR8 += __shfl_xor_sync(0xffffffffu, lR8, 2);

    const size_t pr  = (size_t)(s * BB + b) * TT + rowg;
    const size_t pr8 = pr + 8;
    #pragma unroll
    for (int hb = 0; hb < 8; hb++) {
        *(float2*)&g_pO[pr  * HH + hb * 8 + 2 * c] = make_float2(o[hb][0], o[hb][1]);
        *(float2*)&g_pO[pr8 * HH + hb * 8 + 2 * c] = make_float2(o[hb][2], o[hb][3]);
    }
    if (c == 0) {
        g_pl[pr]  = lR;
        g_pl[pr8] = lR8;
    }
}

// ---------------------------------------------------------------------------
// Kernel 3: merge the four kv-splits (unit weights: common fixed max).
// ---------------------------------------------------------------------------
__global__ __launch_bounds__(256) void combine_kernel(float* __restrict__ out)
{
    const int gid  = blockIdx.x * 256 + threadIdx.x;
    const int rowg = gid >> 4;
    const int col  = (gid & 15) * 4;

    float denom = 0.0f;
    #pragma unroll
    for (int sp = 0; sp < NSPLIT; sp++)
        denom += g_pl[sp * BT + rowg];
    const float inv = 1.0f / denom;

    float4 acc = make_float4(0.f, 0.f, 0.f, 0.f);
    #pragma unroll
    for (int sp = 0; sp < NSPLIT; sp++) {
        float4 O = *(const float4*)&g_pO[((size_t)sp * BT + rowg) * HH + col];
        acc.x += O.x;
        acc.y += O.y;
        acc.z += O.z;
        acc.w += O.w;
    }
    acc.x *= inv; acc.y *= inv; acc.z *= inv; acc.w *= inv;
    *(float4*)&out[(size_t)rowg * HH + col] = acc;
}

// ---------------------------------------------------------------------------
extern "C" void kernel_launch(void* const* d_in, const int* in_sizes, int n_in,
                              void* d_out, int out_size)
{
    const float* x  = (const float*)d_in[0];
    const float* Wq = (const float*)d_in[1];
    const float* Wk = (const float*)d_in[2];
    const float* Wv = (const float*)d_in[3];
    float* out = (float*)d_out;

    const int attn_smem = 3 * 16384;     // 48 KB (3-stage pipeline)
    cudaFuncSetAttribute(attn_kernel, cudaFuncAttributeMaxDynamicSharedMemorySize,
                         attn_smem);

    prep_w<<<(DD * 192 + 255) / 256, 256>>>(Wq, Wk, Wv);
    qkv_mma<<<(BT / 128) * 2, 256>>>(x);
    attn_kernel<<<64 * BB * NSPLIT, 128, attn_smem>>>();
    combine_kernel<<<(BT * HH / 4) / 256, 256>>>(out);
}

// round 16
// speedup vs baseline: 1.6636x; 1.2205x over previous
#include <cuda_runtime.h>
#include <cuda_fp16.h>
#include <cstdint>

#define BB 4
#define TT 4096
#define DD 768
#define HH 64
#define BT (BB*TT)
#define NSPLIT 4
#define MCONST 16.0f

// Scratch.
// g_Qh: fp16, pre-scaled (x0.125*log2e), h PAIR-PERMUTED.
// g_Kh: fp16, h PAIR-PERMUTED.
// g_Vth: fp16, transposed [b][h][t], t PAIR-PERMUTED.
// g_Wf: W (Q|K|V) pre-split into tf32 (hi,lo) and pre-packed in the exact
//       per-fragment float4 layout qkv_mma's MMA consumes:
//       [kt][(kb*24 + nb)*32 + lane] . {x=hi_s0, y=hi_s1, z=lo_s0, w=lo_s1}
__device__ __half g_Qh[BT * HH];
__device__ __half g_Kh[BT * HH];
__device__ __half g_Vth[BB * HH * TT];
__device__ float4 g_Wf[24 * 6144];
__device__ float  g_pO[NSPLIT * BT * HH];   // partial O (scale 2^-MCONST)
__device__ float  g_pl[NSPLIT * BT];        // partial denom (same scale)

// ---------------------------------------------------------------------------
// helpers
// ---------------------------------------------------------------------------
__device__ __forceinline__ uint32_t f2tf(float f) {
    uint32_t u;
    asm("cvt.rna.tf32.f32 %0, %1;" : "=r"(u) : "f"(f));
    return u;
}
__device__ __forceinline__ float tf32f(float f) {
    return __uint_as_float(f2tf(f));
}
__device__ __forceinline__ float ex2(float x) {
    float y;
    asm("ex2.approx.f32 %0, %1;" : "=f"(y) : "f"(x));
    return y;
}
__device__ __forceinline__ uint32_t pack_h2(float lo, float hi) {
    uint32_t u;
    asm("cvt.rn.f16x2.f32 %0, %1, %2;" : "=r"(u) : "f"(hi), "f"(lo));
    return u;
}

__device__ __forceinline__ void mma_tf32(float d[4], const uint32_t a[4],
                                         uint32_t b0, uint32_t b1) {
    asm volatile(
        "mma.sync.aligned.m16n8k8.row.col.f32.tf32.tf32.f32 "
        "{%0,%1,%2,%3}, {%4,%5,%6,%7}, {%8,%9}, {%0,%1,%2,%3};"
        : "+f"(d[0]), "+f"(d[1]), "+f"(d[2]), "+f"(d[3])
        : "r"(a[0]), "r"(a[1]), "r"(a[2]), "r"(a[3]), "r"(b0), "r"(b1));
}

__device__ __forceinline__ void mma_f16(float d[4], const uint32_t a[4],
                                        uint32_t b0, uint32_t b1) {
    asm volatile(
        "mma.sync.aligned.m16n8k16.row.col.f32.f16.f16.f32 "
        "{%0,%1,%2,%3}, {%4,%5,%6,%7}, {%8,%9}, {%0,%1,%2,%3};"
        : "+f"(d[0]), "+f"(d[1]), "+f"(d[2]), "+f"(d[3])
        : "r"(a[0]), "r"(a[1]), "r"(a[2]), "r"(a[3]), "r"(b0), "r"(b1));
}

__device__ __forceinline__ void cpa16(uint32_t smem_dst, const void* gsrc) {
    asm volatile("cp.async.cg.shared.global [%0], [%1], 16;"
                 :: "r"(smem_dst), "l"(gsrc));
}
__device__ __forceinline__ void cpa_commit() {
    asm volatile("cp.async.commit_group;");
}
__device__ __forceinline__ void cpa_wait0() {
    asm volatile("cp.async.wait_group 0;" ::: "memory");
}
__device__ __forceinline__ void cpa_wait1() {
    asm volatile("cp.async.wait_group 1;" ::: "memory");
}

// pair-permuted position for even column `col` within its 16-group
__device__ __forceinline__ int pairperm(int col) {
    const int pg = (col >> 1) & 7;
    const int np = ((pg & 3) << 1) | (pg >> 2);
    return (col & ~15) | (np << 1);
}

// ---------------------------------------------------------------------------
// Kernel 0: split W into (hi, lo) tf32 and scatter into fragment layout.
// ---------------------------------------------------------------------------
__global__ __launch_bounds__(256) void prep_w(
    const float* __restrict__ Wq, const float* __restrict__ Wk,
    const float* __restrict__ Wv)
{
    int i = blockIdx.x * 256 + threadIdx.x;
    if (i >= DD * 192) return;
    int k = i / 192, n = i % 192;
    float v = (n < 64) ? Wq[k * 64 + n]
            : (n < 128) ? Wk[k * 64 + n - 64]
            : Wv[k * 64 + n - 128];
    float hi = tf32f(v);
    float lo = tf32f(v - hi);

    const int kt   = k >> 5;
    const int kk   = k & 31;
    const int kb   = kk >> 3;
    const int kr   = kk & 7;
    const int nb   = n >> 3;
    const int lane = ((n & 7) << 2) | (kr & 3);
    const int slot = kr >> 2;
    float* dst = (float*)&g_Wf[kt * 6144 + (kb * 24 + nb) * 32 + lane];
    dst[slot]     = hi;
    dst[2 + slot] = lo;
}

// ---------------------------------------------------------------------------
// Kernel 1: QKV projection, 2-term tf32 split, FULL cp.async staging:
// x and pre-fragmented W copied async (no scatter, no prefetch regs) ->
// ~120 regs -> 2 CTAs/SM (4 warps/SMSP). 2-stage pipeline.
// smem per stage: xs 128x36 f32 (18432 B) + wf 1536 float4 (24576 B).
// ---------------------------------------------------------------------------
#define QSCALE (0.125f * 1.4426950408889634f)
#define QKV_STAGE_B 43008u   // 18432 + 24576

__global__ __launch_bounds__(256, 2) void qkv_mma(const float* __restrict__ x)
{
    extern __shared__ float qsm[];

    const int tid = threadIdx.x;
    const int w   = tid >> 5;
    const int l   = tid & 31;
    const int mg  = w >> 1;
    const int ng  = w & 1;
    const int row0 = (blockIdx.x >> 1) * 128;
    const int n0   = (blockIdx.x & 1) * 96;
    const int nb0  = (blockIdx.x & 1) * 12;   // W fragment nb offset

    float acc[2][6][4];
    #pragma unroll
    for (int mt = 0; mt < 2; mt++)
        #pragma unroll
        for (int nb = 0; nb < 6; nb++)
            acc[mt][nb][0] = acc[mt][nb][1] = acc[mt][nb][2] = acc[mt][nb][3] = 0.0f;

    const uint32_t sb = (uint32_t)__cvta_generic_to_shared(qsm);

    // staging coords
    const int xrow = tid >> 3;        // 0..31 (+32i)
    const int xcq  = tid & 7;

    auto issue = [&](int st, int k0) {
        const uint32_t base = sb + (uint32_t)st * QKV_STAGE_B;
        // x tile: 128 rows x 32 floats = 1024 chunks, 4 per thread
        #pragma unroll
        for (int t = 0; t < 4; t++) {
            const int row = xrow + t * 32;
            cpa16(base + (uint32_t)row * 144u + (uint32_t)xcq * 16u,
                  &x[(size_t)(row0 + row) * DD + k0 + xcq * 4]);
        }
        // W fragments: 1536 float4, 6 per thread (contiguous per kb chunk)
        const int kt = k0 >> 5;
        #pragma unroll
        for (int j = 0; j < 6; j++) {
            const int idx = tid + j * 256;          // 0..1535
            const int kb  = idx / 384;
            const int off = idx - kb * 384;
            cpa16(base + 18432u + (uint32_t)idx * 16u,
                  (const char*)g_Wf + (size_t)(kt * 6144 + kb * 768 + nb0 * 32 + off) * 16);
        }
        cpa_commit();
    };

    issue(0, 0);
    int cur = 0;

    for (int k0 = 0; k0 < DD; k0 += 32) {
        cpa_wait0();
        __syncthreads();                 // stage cur ready; cur^1 fully consumed
        if (k0 + 32 < DD) issue(cur ^ 1, k0 + 32);

        const float*  xs = qsm + cur * (QKV_STAGE_B / 4);
        const float4* wf = (const float4*)(xs + 128 * 36);

        #pragma unroll
        for (int kb = 0; kb < 4; kb++) {
            uint32_t ahi[2][4];
            #pragma unroll
            for (int mt = 0; mt < 2; mt++) {
                const int rA = mg * 32 + mt * 16 + (l >> 2);
                const int cA = kb * 8 + (l & 3);
                ahi[mt][0] = f2tf(xs[rA * 36 + cA]);
                ahi[mt][1] = f2tf(xs[(rA + 8) * 36 + cA]);
                ahi[mt][2] = f2tf(xs[rA * 36 + cA + 4]);
                ahi[mt][3] = f2tf(xs[(rA + 8) * 36 + cA + 4]);
            }
            #pragma unroll
            for (int nb = 0; nb < 6; nb++) {
                float4 q = wf[(kb * 12 + ng * 6 + nb) * 32 + l];
                uint32_t bh0 = __float_as_uint(q.x), bh1 = __float_as_uint(q.y);
                uint32_t bl0 = __float_as_uint(q.z), bl1 = __float_as_uint(q.w);
                #pragma unroll
                for (int mt = 0; mt < 2; mt++) {
                    mma_tf32(acc[mt][nb], ahi[mt], bh0, bh1);
                    mma_tf32(acc[mt][nb], ahi[mt], bl0, bl1);
                }
            }
        }
        cur ^= 1;
    }

    #pragma unroll
    for (int mt = 0; mt < 2; mt++) {
        #pragma unroll
        for (int nb = 0; nb < 6; nb++) {
            const int rowa  = row0 + mg * 32 + mt * 16 + (l >> 2);
            const int nglob = n0 + ng * 48 + nb * 8 + (l & 3) * 2;
            const int mat   = nglob >> 6;
            const int col   = nglob & 63;
            if (mat == 0) {
                const int pos = pairperm(col);
                g_Qh[(size_t)rowa * HH + pos]           = __float2half_rn(QSCALE * acc[mt][nb][0]);
                g_Qh[(size_t)rowa * HH + pos + 1]       = __float2half_rn(QSCALE * acc[mt][nb][1]);
                g_Qh[(size_t)(rowa + 8) * HH + pos]     = __float2half_rn(QSCALE * acc[mt][nb][2]);
                g_Qh[(size_t)(rowa + 8) * HH + pos + 1] = __float2half_rn(QSCALE * acc[mt][nb][3]);
            } else if (mat == 1) {
                const int pos = pairperm(col);
                g_Kh[(size_t)rowa * HH + pos]           = __float2half_rn(acc[mt][nb][0]);
                g_Kh[(size_t)rowa * HH + pos + 1]       = __float2half_rn(acc[mt][nb][1]);
                g_Kh[(size_t)(rowa + 8) * HH + pos]     = __float2half_rn(acc[mt][nb][2]);
                g_Kh[(size_t)(rowa + 8) * HH + pos + 1] = __float2half_rn(acc[mt][nb][3]);
            } else {
                const int bb = rowa >> 12;
                const int t0 = rowa & 4095;
                const int q2 = (t0 >> 1) & 3;
                const int tp = (t0 & ~15) | (q2 << 2) | (t0 & 1);
                __half* v0 = g_Vth + (size_t)((bb << 6) + col) * TT;
                __half* v1 = g_Vth + (size_t)((bb << 6) + col + 1) * TT;
                v0[tp]     = __float2half_rn(acc[mt][nb][0]);
                v1[tp]     = __float2half_rn(acc[mt][nb][1]);
                v0[tp + 2] = __float2half_rn(acc[mt][nb][2]);
                v1[tp + 2] = __float2half_rn(acc[mt][nb][3]);
            }
        }
    }
}

// ---------------------------------------------------------------------------
// Kernel 2: causal flash attention (unchanged from R15): split-kv (4),
// fixed-max softmax, fp16 MMAs, 3-stage cp.async pipeline, 4 CTAs/SM.
// ---------------------------------------------------------------------------
__global__ __launch_bounds__(128, 4) void attn_kernel()
{
    extern __shared__ __half smh[];   // [3 bufs][K 4096 | V 4096] halves

    const int tid = threadIdx.x;
    const int w   = tid >> 5;
    const int l   = tid & 31;
    const int r   = l >> 2;
    const int c   = l & 3;

    const int bid = blockIdx.x;
    const int qt  = 63 - (bid >> 4);
    const int b   = (bid >> 2) & 3;
    const int s   = bid & 3;
    const int q0  = qt * 64;
    const size_t base = (size_t)b * TT * HH;

    const int nt    = qt + 1;
    const int chunk = (nt + NSPLIT - 1) >> 2;
    const int ktbeg = min(s * chunk, nt);
    const int ktend = min(ktbeg + chunk, nt);

    const int rowg  = q0 + w * 16 + r;
    const int rowg8 = rowg + 8;

    float o[8][4];
    #pragma unroll
    for (int hb = 0; hb < 8; hb++)
        o[hb][0] = o[hb][1] = o[hb][2] = o[hb][3] = 0.0f;
    float lR = 0.0f, lR8 = 0.0f;

    if (ktbeg < ktend) {
        const uint32_t sb = (uint32_t)__cvta_generic_to_shared(smh);

        const int crow = tid >> 3;
        const int ch   = tid & 7;

        uint32_t qf[4][4];
        #pragma unroll
        for (int kb = 0; kb < 4; kb++) {
            uint2 u0 = *(const uint2*)&g_Qh[base + (size_t)rowg  * HH + kb * 16 + 4 * c];
            uint2 u1 = *(const uint2*)&g_Qh[base + (size_t)rowg8 * HH + kb * 16 + 4 * c];
            qf[kb][0] = u0.x;
            qf[kb][1] = u1.x;
            qf[kb][2] = u0.y;
            qf[kb][3] = u1.y;
        }

        auto issue = [&](int bf, int jb) {
            #pragma unroll
            for (int i = 0; i < 4; i++) {
                const int row = crow + i * 16;
                const uint32_t swz = (uint32_t)((ch ^ ((row & 3) << 1)) << 4);
                cpa16(sb + (uint32_t)bf * 16384u + (uint32_t)row * 128u + swz,
                      g_Kh + base + (size_t)(jb + row) * HH + ch * 8);
                cpa16(sb + (uint32_t)bf * 16384u + 8192u + (uint32_t)row * 128u + swz,
                      g_Vth + (size_t)((b << 6) + row) * TT + jb + ch * 8);
            }
            cpa_commit();
        };

        issue(0, ktbeg * 64);
        if (ktbeg + 1 < ktend) issue(1, (ktbeg + 1) * 64);

        int bi = 0;
        const int rx   = (r & 3) << 1;
        const int cc   = c >> 1;
        const int hoff = (c & 1) * 4;

        for (int kt = ktbeg; kt < ktend; kt++) {
            const int jbase = kt * 64;
            if (kt + 1 < ktend) cpa_wait1();
            else                cpa_wait0();
            __syncthreads();
            if (kt + 2 < ktend) {
                int nb2 = bi + 2; if (nb2 >= 3) nb2 -= 3;
                issue(nb2, (kt + 2) * 64);
            }

            const __half* kp = smh + bi * 8192;
            const __half* vp = kp + 4096;

            float sS[8][4];
            #pragma unroll
            for (int nb = 0; nb < 8; nb++)
                sS[nb][0] = sS[nb][1] = sS[nb][2] = sS[nb][3] = 0.0f;
            #pragma unroll
            for (int nb = 0; nb < 8; nb++) {
                const __half* krow = kp + (nb * 8 + r) * 64;
                #pragma unroll
                for (int kb = 0; kb < 4; kb++) {
                    uint2 bk = *(const uint2*)&krow[(((2 * kb + cc) ^ rx) << 3) + hoff];
                    mma_f16(sS[nb], qf[kb], bk.x, bk.y);
                }
            }

            if (kt == qt) {
                #pragma unroll
                for (int nb = 0; nb < 8; nb++) {
                    const int col = jbase + nb * 8 + 2 * c;
                    if (col     > rowg ) sS[nb][0] = -1.0e30f;
                    if (col + 1 > rowg ) sS[nb][1] = -1.0e30f;
                    if (col     > rowg8) sS[nb][2] = -1.0e30f;
                    if (col + 1 > rowg8) sS[nb][3] = -1.0e30f;
                }
            }

            float sum0 = 0.0f, sum1 = 0.0f;
            #pragma unroll
            for (int nb = 0; nb < 8; nb++) {
                sS[nb][0] = ex2(sS[nb][0] - MCONST);
                sS[nb][1] = ex2(sS[nb][1] - MCONST);
                sS[nb][2] = ex2(sS[nb][2] - MCONST);
                sS[nb][3] = ex2(sS[nb][3] - MCONST);
                sum0 += sS[nb][0] + sS[nb][1];
                sum1 += sS[nb][2] + sS[nb][3];
            }
            lR  += sum0;
            lR8 += sum1;

            #pragma unroll
            for (int kb = 0; kb < 4; kb++) {
                uint32_t a[4];
                a[0] = pack_h2(sS[2 * kb    ][0], sS[2 * kb    ][1]);
                a[1] = pack_h2(sS[2 * kb    ][2], sS[2 * kb    ][3]);
                a[2] = pack_h2(sS[2 * kb + 1][0], sS[2 * kb + 1][1]);
                a[3] = pack_h2(sS[2 * kb + 1][2], sS[2 * kb + 1][3]);
                #pragma unroll
                for (int hb = 0; hb < 8; hb++) {
                    const __half* vrow = vp + (hb * 8 + r) * 64;
                    uint2 bv = *(const uint2*)&vrow[(((2 * kb + cc) ^ rx) << 3) + hoff];
                    mma_f16(o[hb], a, bv.x, bv.y);
                }
            }
            bi = (bi == 2) ? 0 : bi + 1;
        }
    }

    lR  += __shfl_xor_sync(0xffffffffu, lR, 1);
    lR  += __shfl_xor_sync(0xffffffffu, lR, 2);
    lR8 += __shfl_xor_sync(0xffffffffu, lR8, 1);
    lR8 += __shfl_xor_sync(0xffffffffu, lR8, 2);

    const size_t pr  = (size_t)(s * BB + b) * TT + rowg;
    const size_t pr8 = pr + 8;
    #pragma unroll
    for (int hb = 0; hb < 8; hb++) {
        *(float2*)&g_pO[pr  * HH + hb * 8 + 2 * c] = make_float2(o[hb][0], o[hb][1]);
        *(float2*)&g_pO[pr8 * HH + hb * 8 + 2 * c] = make_float2(o[hb][2], o[hb][3]);
    }
    if (c == 0) {
        g_pl[pr]  = lR;
        g_pl[pr8] = lR8;
    }
}

// ---------------------------------------------------------------------------
// Kernel 3: merge the four kv-splits (unit weights: common fixed max).
// ---------------------------------------------------------------------------
__global__ __launch_bounds__(256) void combine_kernel(float* __restrict__ out)
{
    const int gid  = blockIdx.x * 256 + threadIdx.x;
    const int rowg = gid >> 4;
    const int col  = (gid & 15) * 4;

    float denom = 0.0f;
    #pragma unroll
    for (int sp = 0; sp < NSPLIT; sp++)
        denom += g_pl[sp * BT + rowg];
    const float inv = 1.0f / denom;

    float4 acc = make_float4(0.f, 0.f, 0.f, 0.f);
    #pragma unroll
    for (int sp = 0; sp < NSPLIT; sp++) {
        float4 O = *(const float4*)&g_pO[((size_t)sp * BT + rowg) * HH + col];
        acc.x += O.x;
        acc.y += O.y;
        acc.z += O.z;
        acc.w += O.w;
    }
    acc.x *= inv; acc.y *= inv; acc.z *= inv; acc.w *= inv;
    *(float4*)&out[(size_t)rowg * HH + col] = acc;
}

// ---------------------------------------------------------------------------
extern "C" void kernel_launch(void* const* d_in, const int* in_sizes, int n_in,
                              void* d_out, int out_size)
{
    const float* x  = (const float*)d_in[0];
    const float* Wq = (const float*)d_in[1];
    const float* Wk = (const float*)d_in[2];
    const float* Wv = (const float*)d_in[3];
    float* out = (float*)d_out;

    const int attn_smem = 3 * 16384;           // 48 KB
    const int qkv_smem  = 2 * (int)QKV_STAGE_B; // 86016 B
    cudaFuncSetAttribute(attn_kernel, cudaFuncAttributeMaxDynamicSharedMemorySize,
                         attn_smem);
    cudaFuncSetAttribute(qkv_mma, cudaFuncAttributeMaxDynamicSharedMemorySize,
                         qkv_smem);

    prep_w<<<(DD * 192 + 255) / 256, 256>>>(Wq, Wk, Wv);
    qkv_mma<<<(BT / 128) * 2, 256, qkv_smem>>>(x);
    attn_kernel<<<64 * BB * NSPLIT, 128, attn_smem>>>();
    combine_kernel<<<(BT * HH / 4) / 256, 256>>>(out);
}